// round 1
// baseline (speedup 1.0000x reference)
#include <cuda_runtime.h>
#include <cuda_bf16.h>
#include <math.h>

// ---------------- problem constants ----------------
#define BB   4
#define LL   2048
#define LCC  512
#define CC   1024
#define CTXC 1024
#define HH   16
#define DD   64
#define SIXC (6*CC)
#define MT   (BB*LL)          // 8192 token rows
#define EPS  1e-6f
#define ATT_SCALE 0.125f      // 1/sqrt(64)

// ---------------- device scratch (no allocations allowed) ----------------
__device__ float g_h  [(long long)MT * CC];        // LN outputs       (33.5 MB)
__device__ float g_qkv[(long long)MT * 3 * CC];    // qkv / q2 reuse   (100 MB)
__device__ float g_S  [(long long)HH * LL * LL];   // scores / FFN mid (268 MB)
__device__ float g_O  [(long long)MT * CC];        // attention output (33.5 MB)
__device__ float g_t  [(long long)MT * CC];        // projection temp  (33.5 MB)
__device__ float g_kv [(long long)BB * LCC * 2 * CC]; // cross kv      (16.8 MB)
__device__ float g_ada[(long long)BB * SIXC];      // modulation

// ---------------- generic batched SGEMM ----------------
// C[z] = alpha * A[z] (MxK) * B[z] (KxN, TRANSB: B stored NxK) + bias
#define BM 128
#define BN 128
#define BKK 8

template<int TRANSB>
__global__ __launch_bounds__(256)
void sgemm_kernel(const float* __restrict__ A, const float* __restrict__ Bp,
                  const float* __restrict__ bias, float* __restrict__ Cp,
                  int M, int N, int K, int lda, int ldb, int ldc,
                  long long strideA, long long strideB, long long strideC,
                  float alpha)
{
    __shared__ float As[BKK][BM];
    __shared__ float Bs[BKK][BN];

    const int z = blockIdx.z;
    const float* Ab = A  + (long long)z * strideA;
    const float* Bb = Bp + (long long)z * strideB;
    float*       Cb = Cp + (long long)z * strideC;

    const int t  = threadIdx.x;                 // 0..255
    const int m0 = blockIdx.y * BM;
    const int n0 = blockIdx.x * BN;

    const int a_row = t >> 1;                   // 0..127
    const int a_kc  = (t & 1) * 4;              // 0 or 4
    const int bk_row = t >> 5;                  // 0..7   (NN)
    const int bk_col = (t & 31) * 4;            // 0..124 (NN)

    const int tx = t & 15, ty = t >> 4;

    float acc[8][8];
    #pragma unroll
    for (int i = 0; i < 8; i++)
        #pragma unroll
        for (int j = 0; j < 8; j++) acc[i][j] = 0.f;

    for (int kt = 0; kt < K; kt += BKK) {
        // load A tile (transposed into smem)
        #pragma unroll
        for (int i = 0; i < 4; i++) {
            int mg = m0 + a_row, kg = kt + a_kc + i;
            As[a_kc + i][a_row] = (mg < M && kg < K) ? Ab[(long long)mg * lda + kg] : 0.f;
        }
        // load B tile
        if (TRANSB) {
            #pragma unroll
            for (int i = 0; i < 4; i++) {
                int ng = n0 + a_row, kg = kt + a_kc + i;
                Bs[a_kc + i][a_row] = (ng < N && kg < K) ? Bb[(long long)ng * ldb + kg] : 0.f;
            }
        } else {
            #pragma unroll
            for (int i = 0; i < 4; i++) {
                int kg = kt + bk_row, ng = n0 + bk_col + i;
                Bs[bk_row][bk_col + i] = (kg < K && ng < N) ? Bb[(long long)kg * ldb + ng] : 0.f;
            }
        }
        __syncthreads();

        #pragma unroll
        for (int kk = 0; kk < BKK; kk++) {
            float af[8], bf[8];
            #pragma unroll
            for (int i = 0; i < 8; i++) af[i] = As[kk][ty * 8 + i];
            #pragma unroll
            for (int j = 0; j < 8; j++) bf[j] = Bs[kk][tx * 8 + j];
            #pragma unroll
            for (int i = 0; i < 8; i++)
                #pragma unroll
                for (int j = 0; j < 8; j++)
                    acc[i][j] = fmaf(af[i], bf[j], acc[i][j]);
        }
        __syncthreads();
    }

    #pragma unroll
    for (int i = 0; i < 8; i++) {
        int mg = m0 + ty * 8 + i;
        if (mg >= M) continue;
        #pragma unroll
        for (int j = 0; j < 8; j++) {
            int ng = n0 + tx * 8 + j;
            if (ng >= N) continue;
            float v = acc[i][j] * alpha;
            if (bias) v += bias[ng];
            Cb[(long long)mg * ldc + ng] = v;
        }
    }
}

// ---------------- LayerNorm (+optional modulation) ----------------
// out = (x - mu) * rsqrt(var+eps) * (add_one + gamma[b*gstride + c]) + beta[b*gstride + c]
__global__ __launch_bounds__(256)
void ln_kernel(const float* __restrict__ x, float* __restrict__ out,
               const float* __restrict__ gamma, const float* __restrict__ beta,
               int gstride, float add_one)
{
    const int row = blockIdx.x;          // b*L + l
    const int b   = row / LL;
    const float* px = x + (long long)row * CC;
    float*       po = out + (long long)row * CC;
    const int t = threadIdx.x;

    float v[4];
    float s = 0.f, s2 = 0.f;
    #pragma unroll
    for (int i = 0; i < 4; i++) {
        v[i] = px[t + i * 256];
        s  += v[i];
        s2 += v[i] * v[i];
    }
    __shared__ float sred[2][8];
    #pragma unroll
    for (int o = 16; o; o >>= 1) {
        s  += __shfl_xor_sync(0xffffffffu, s,  o);
        s2 += __shfl_xor_sync(0xffffffffu, s2, o);
    }
    if ((t & 31) == 0) { sred[0][t >> 5] = s; sred[1][t >> 5] = s2; }
    __syncthreads();
    s = 0.f; s2 = 0.f;
    #pragma unroll
    for (int w = 0; w < 8; w++) { s += sred[0][w]; s2 += sred[1][w]; }

    const float mu  = s * (1.f / CC);
    const float var = s2 * (1.f / CC) - mu * mu;
    const float r   = rsqrtf(var + EPS);

    const float* g  = gamma + (long long)b * gstride;
    const float* be = beta  + (long long)b * gstride;
    #pragma unroll
    for (int i = 0; i < 4; i++) {
        int c = t + i * 256;
        po[c] = (v[i] - mu) * r * (add_one + g[c]) + be[c];
    }
}

// ---------------- row softmax (in place), len = NPT*256 ----------------
template<int NPT>
__global__ __launch_bounds__(256)
void softmax_kernel(float* __restrict__ S)
{
    const int len = NPT * 256;
    float* p = S + (long long)blockIdx.x * len;
    const int t = threadIdx.x;

    float v[NPT];
    float mx = -1e30f;
    #pragma unroll
    for (int i = 0; i < NPT; i++) { v[i] = p[t + i * 256]; mx = fmaxf(mx, v[i]); }

    __shared__ float sred[8];
    #pragma unroll
    for (int o = 16; o; o >>= 1) mx = fmaxf(mx, __shfl_xor_sync(0xffffffffu, mx, o));
    if ((t & 31) == 0) sred[t >> 5] = mx;
    __syncthreads();
    float bm = sred[0];
    #pragma unroll
    for (int w = 1; w < 8; w++) bm = fmaxf(bm, sred[w]);
    __syncthreads();

    float s = 0.f;
    #pragma unroll
    for (int i = 0; i < NPT; i++) { v[i] = __expf(v[i] - bm); s += v[i]; }
    #pragma unroll
    for (int o = 16; o; o >>= 1) s += __shfl_xor_sync(0xffffffffu, s, o);
    if ((t & 31) == 0) sred[t >> 5] = s;
    __syncthreads();
    float bs = 0.f;
    #pragma unroll
    for (int w = 0; w < 8; w++) bs += sred[w];

    const float inv = 1.f / bs;
    #pragma unroll
    for (int i = 0; i < NPT; i++) p[t + i * 256] = v[i] * inv;
}

// ---------------- residual (+ optional per-(b,c) gate) ----------------
__global__ __launch_bounds__(256)
void residual_kernel(const float* __restrict__ base, const float* __restrict__ tt,
                     const float* __restrict__ gate, int gstride,
                     float* __restrict__ out)
{
    long long i = (long long)blockIdx.x * 256 + threadIdx.x;
    float g = 1.f;
    if (gate) {
        int b = (int)(i >> 21);        // L*C = 2^21
        int c = (int)(i & 1023);       // C   = 2^10
        g = gate[b * gstride + c];
    }
    out[i] = base[i] + tt[i] * g;
}

// ---------------- exact GELU ----------------
__global__ __launch_bounds__(256)
void gelu_kernel(float* __restrict__ p)
{
    long long i = (long long)blockIdx.x * 256 + threadIdx.x;
    float x = p[i];
    p[i] = 0.5f * x * (1.f + erff(x * 0.70710678118654752f));
}

// ---------------- adaLN: ada = silu(mod) @ w_ada + b_ada ----------------
__global__ __launch_bounds__(256)
void ada_kernel(const float* __restrict__ mod, const float* __restrict__ w,
                const float* __restrict__ bias, float* __restrict__ ada)
{
    __shared__ float sm[CC];
    const int b = blockIdx.y;
    const int j = blockIdx.x * 256 + threadIdx.x;   // 0..6143
    #pragma unroll
    for (int i = 0; i < 4; i++) {
        int c = threadIdx.x + i * 256;
        float m = mod[b * CC + c];
        sm[c] = m / (1.f + expf(-m));
    }
    __syncthreads();
    float acc = 0.f;
    for (int c = 0; c < CC; c++)
        acc = fmaf(sm[c], w[(long long)c * SIXC + j], acc);
    ada[(long long)b * SIXC + j] = acc + bias[j];
}

// ---------------- launch ----------------
extern "C" void kernel_launch(void* const* d_in, const int* in_sizes, int n_in,
                              void* d_out, int out_size)
{
    const float* x      = (const float*)d_in[0];
    const float* mod    = (const float*)d_in[1];
    const float* ctx    = (const float*)d_in[2];
    const float* w_ada  = (const float*)d_in[3];
    const float* b_ada  = (const float*)d_in[4];
    const float* w_qkv  = (const float*)d_in[5];
    const float* b_qkv  = (const float*)d_in[6];
    const float* w_so   = (const float*)d_in[7];
    const float* b_so   = (const float*)d_in[8];
    const float* gn2    = (const float*)d_in[9];
    const float* bn2    = (const float*)d_in[10];
    const float* w_cq   = (const float*)d_in[11];
    const float* b_cq   = (const float*)d_in[12];
    const float* w_ckv  = (const float*)d_in[13];
    const float* b_ckv  = (const float*)d_in[14];
    const float* w_co   = (const float*)d_in[15];
    const float* b_co   = (const float*)d_in[16];
    const float* w_m1   = (const float*)d_in[17];
    const float* b_m1   = (const float*)d_in[18];
    const float* w_m2   = (const float*)d_in[19];
    const float* b_m2   = (const float*)d_in[20];
    float* out = (float*)d_out;

    float *ph, *pqkv, *pS, *pO, *pt, *pkv, *pada;
    cudaGetSymbolAddress((void**)&ph,   g_h);
    cudaGetSymbolAddress((void**)&pqkv, g_qkv);
    cudaGetSymbolAddress((void**)&pS,   g_S);
    cudaGetSymbolAddress((void**)&pO,   g_O);
    cudaGetSymbolAddress((void**)&pt,   g_t);
    cudaGetSymbolAddress((void**)&pkv,  g_kv);
    cudaGetSymbolAddress((void**)&pada, g_ada);

    const long long totalBLC = (long long)MT * CC;      // 8,388,608
    const int resGrid  = (int)(totalBLC / 256);
    const int geluGrid = (int)(((long long)MT * 4 * CC) / 256);

    // 1. adaLN modulation
    ada_kernel<<<dim3(SIXC / 256, BB), 256>>>(mod, w_ada, b_ada, pada);

    // ===== MSA branch =====
    // h = LN(x)*(1+sc_msa) + sh_msa    (sc at +C, sh at +0, per-batch stride 6C)
    ln_kernel<<<MT, 256>>>(x, ph, pada + CC, pada, SIXC, 1.f);
    // qkv = h @ w_qkv + b_qkv
    sgemm_kernel<0><<<dim3(3 * CC / BN, MT / BM, 1), 256>>>(
        ph, w_qkv, b_qkv, pqkv, MT, 3 * CC, CC, CC, 3 * CC, 3 * CC, 0, 0, 0, 1.f);

    for (int b = 0; b < BB; b++) {
        const float* qb = pqkv + (long long)b * LL * 3 * CC;
        // S = Q K^T * scale   (batched over 16 heads)
        sgemm_kernel<1><<<dim3(LL / BN, LL / BM, HH), 256>>>(
            qb, qb + CC, nullptr, pS,
            LL, LL, DD, 3 * CC, 3 * CC, LL,
            DD, DD, (long long)LL * LL, ATT_SCALE);
        softmax_kernel<8><<<HH * LL, 256>>>(pS);
        // O = P V
        sgemm_kernel<0><<<dim3(1, LL / BM, HH), 256>>>(
            pS, qb + 2 * CC, nullptr, pO + (long long)b * LL * CC,
            LL, DD, LL, LL, 3 * CC, CC,
            (long long)LL * LL, DD, DD, 1.f);
    }
    // t = O @ w_so + b_so
    sgemm_kernel<0><<<dim3(CC / BN, MT / BM, 1), 256>>>(
        pO, w_so, b_so, pt, MT, CC, CC, CC, CC, CC, 0, 0, 0, 1.f);
    // x1 = x + t * g_msa   (gate at +2C)
    residual_kernel<<<resGrid, 256>>>(x, pt, pada + 2 * CC, SIXC, out);

    // ===== MCA branch =====
    // h = LN(x1) * g_n2 + b_n2
    ln_kernel<<<MT, 256>>>(out, ph, gn2, bn2, 0, 0.f);
    // q2 = h @ w_cq + b_cq  (reuse g_qkv)
    sgemm_kernel<0><<<dim3(CC / BN, MT / BM, 1), 256>>>(
        ph, w_cq, b_cq, pqkv, MT, CC, CC, CC, CC, CC, 0, 0, 0, 1.f);
    // kv = context @ w_ckv + b_ckv
    sgemm_kernel<0><<<dim3(2 * CC / BN, (BB * LCC) / BM, 1), 256>>>(
        ctx, w_ckv, b_ckv, pkv, BB * LCC, 2 * CC, CTXC, CTXC, 2 * CC, 2 * CC, 0, 0, 0, 1.f);

    for (int b = 0; b < BB; b++) {
        const float* q2b = pqkv + (long long)b * LL * CC;
        const float* kvb = pkv + (long long)b * LCC * 2 * CC;
        sgemm_kernel<1><<<dim3(LCC / BN, LL / BM, HH), 256>>>(
            q2b, kvb, nullptr, pS,
            LL, LCC, DD, CC, 2 * CC, LCC,
            DD, DD, (long long)LL * LCC, ATT_SCALE);
        softmax_kernel<2><<<HH * LL, 256>>>(pS);
        sgemm_kernel<0><<<dim3(1, LL / BM, HH), 256>>>(
            pS, kvb + CC, nullptr, pO + (long long)b * LL * CC,
            LL, DD, LCC, LCC, 2 * CC, CC,
            (long long)LL * LCC, DD, DD, 1.f);
    }
    // t = O @ w_co + b_co
    sgemm_kernel<0><<<dim3(CC / BN, MT / BM, 1), 256>>>(
        pO, w_co, b_co, pt, MT, CC, CC, CC, CC, CC, 0, 0, 0, 1.f);
    // x2 = x1 + t
    residual_kernel<<<resGrid, 256>>>(out, pt, nullptr, 0, out);

    // ===== FFN branch =====
    // h = LN(x2)*(1+sc_mlp) + sh_mlp   (sc at +4C, sh at +3C)
    ln_kernel<<<MT, 256>>>(out, ph, pada + 4 * CC, pada + 3 * CC, SIXC, 1.f);
    // m = h @ w_m1 + b_m1   (into g_S scratch, 134MB < 268MB)
    sgemm_kernel<0><<<dim3(4 * CC / BN, MT / BM, 1), 256>>>(
        ph, w_m1, b_m1, pS, MT, 4 * CC, CC, CC, 4 * CC, 4 * CC, 0, 0, 0, 1.f);
    gelu_kernel<<<geluGrid, 256>>>(pS);
    // t = m @ w_m2 + b_m2
    sgemm_kernel<0><<<dim3(CC / BN, MT / BM, 1), 256>>>(
        pS, w_m2, b_m2, pt, MT, CC, 4 * CC, 4 * CC, CC, CC, 0, 0, 0, 1.f);
    // x3 = x2 + t * g_mlp   (gate at +5C)
    residual_kernel<<<resGrid, 256>>>(out, pt, pada + 5 * CC, SIXC, out);
}

// round 2
// speedup vs baseline: 3.1209x; 3.1209x over previous
#include <cuda_runtime.h>
#include <cuda_bf16.h>
#include <math.h>
#include <stdint.h>

// ---------------- problem constants ----------------
#define BB   4
#define LL   2048
#define LCC  512
#define CC   1024
#define CTXC 1024
#define HH   16
#define DD   64
#define SIXC (6*CC)
#define MT   (BB*LL)          // 8192 token rows
#define EPS  1e-6f
#define ATT_SCALE 0.125f      // 1/sqrt(64)

// ---------------- device scratch (no allocations allowed) ----------------
__device__ float g_h  [(long long)MT * CC];        // LN outputs       (33.5 MB)
__device__ float g_qkv[(long long)MT * 3 * CC];    // qkv / q2 reuse   (100 MB)
__device__ float g_S  [(long long)HH * LL * LL];   // scores / FFN mid (268 MB)
__device__ float g_O  [(long long)MT * CC];        // attention output (33.5 MB)
__device__ float g_t  [(long long)MT * CC];        // projection temp  (33.5 MB)
__device__ float g_kv [(long long)BB * LCC * 2 * CC]; // cross kv      (16.8 MB)
__device__ float g_ada[(long long)BB * SIXC];      // modulation

// ---------------- tf32 helpers ----------------
__device__ __forceinline__ float tf32r(float x) {
    uint32_t u;
    asm("cvt.rna.tf32.f32 %0, %1;" : "=r"(u) : "f"(x));
    return __uint_as_float(u);
}

#define MMA_TF32(d, a, b)                                                     \
    asm volatile("mma.sync.aligned.m16n8k8.row.col.f32.tf32.tf32.f32 "        \
                 "{%0,%1,%2,%3}, {%4,%5,%6,%7}, {%8,%9}, {%0,%1,%2,%3};\n"    \
                 : "+f"((d)[0]), "+f"((d)[1]), "+f"((d)[2]), "+f"((d)[3])     \
                 : "r"((a)[0]), "r"((a)[1]), "r"((a)[2]), "r"((a)[3]),        \
                   "r"((b)[0]), "r"((b)[1]))

// ---------------- generic batched tf32 tensor-core GEMM ----------------
// C[z] = alpha * A[z] (MxK, row-major) * B[z] (KxN; TRANSB: stored NxK) + bias
// Requirements (all satisfied by every call site): M % 128 == 0, N % BN == 0,
// K % 16 == 0, all leading dims % 4 == 0, 16B-aligned base pointers.
#define TBM 128
#define TBK 16

template<int TRANSB, int BN>
__global__ __launch_bounds__(256, 2)
void tgemm_kernel(const float* __restrict__ A, const float* __restrict__ Bp,
                  const float* __restrict__ bias, float* __restrict__ Cp,
                  int M, int N, int K, int lda, int ldb, int ldc,
                  long long strideA, long long strideB, long long strideC,
                  float alpha)
{
    // k-major shared tiles, +8 pad => fragment LDS is bank-conflict-free
    __shared__ float As[TBK][TBM + 8];
    __shared__ float Bs[TBK][BN + 8];

    constexpr int WARPS_N = BN / 32;          // 4 (BN=128) or 2 (BN=64)
    constexpr int WARPS_M = 8 / WARPS_N;      // 2 or 4
    constexpr int WM = TBM / WARPS_M;         // 64 or 32
    constexpr int M_AT = WM / 16;             // 4 or 2
    constexpr int N_AT = 4;                   // 32 / 8

    const int z = blockIdx.z;
    const float* Ab = A  + (long long)z * strideA;
    const float* Bb = Bp + (long long)z * strideB;
    float*       Cb = Cp + (long long)z * strideC;

    const int t    = threadIdx.x;
    const int m0   = blockIdx.y * TBM;
    const int n0   = blockIdx.x * BN;
    const int lane = t & 31;
    const int warp = t >> 5;
    const int qr   = lane >> 2;   // 0..7
    const int qc   = lane & 3;    // 0..3
    const int wm   = warp / WARPS_N;
    const int wn   = warp % WARPS_N;
    const int rb   = wm * WM;     // warp m-base in tile
    const int nb   = wn * 32;     // warp n-base in tile

    float acc[M_AT][N_AT][4];
    #pragma unroll
    for (int i = 0; i < M_AT; i++)
        #pragma unroll
        for (int j = 0; j < N_AT; j++)
            #pragma unroll
            for (int r = 0; r < 4; r++) acc[i][j][r] = 0.f;

    // per-thread load coordinates
    const int a_r  = t >> 1;                 // 0..127
    const int a_kc = (t & 1) * 8;

    for (int kt = 0; kt < K; kt += TBK) {
        // ---- load A tile (transpose to k-major, convert to tf32) ----
        {
            const float4* p = reinterpret_cast<const float4*>(
                Ab + (long long)(m0 + a_r) * lda + kt + a_kc);
            float4 v0 = p[0], v1 = p[1];
            As[a_kc + 0][a_r] = tf32r(v0.x);
            As[a_kc + 1][a_r] = tf32r(v0.y);
            As[a_kc + 2][a_r] = tf32r(v0.z);
            As[a_kc + 3][a_r] = tf32r(v0.w);
            As[a_kc + 4][a_r] = tf32r(v1.x);
            As[a_kc + 5][a_r] = tf32r(v1.y);
            As[a_kc + 6][a_r] = tf32r(v1.z);
            As[a_kc + 7][a_r] = tf32r(v1.w);
        }
        // ---- load B tile ----
        if (TRANSB) {
            if (BN == 128) {
                const int r = t >> 1, kc = (t & 1) * 8;
                const float4* p = reinterpret_cast<const float4*>(
                    Bb + (long long)(n0 + r) * ldb + kt + kc);
                float4 v0 = p[0], v1 = p[1];
                Bs[kc + 0][r] = tf32r(v0.x);
                Bs[kc + 1][r] = tf32r(v0.y);
                Bs[kc + 2][r] = tf32r(v0.z);
                Bs[kc + 3][r] = tf32r(v0.w);
                Bs[kc + 4][r] = tf32r(v1.x);
                Bs[kc + 5][r] = tf32r(v1.y);
                Bs[kc + 6][r] = tf32r(v1.z);
                Bs[kc + 7][r] = tf32r(v1.w);
            } else {  // BN == 64
                const int r = t >> 2, kc = (t & 3) * 4;
                float4 v = *reinterpret_cast<const float4*>(
                    Bb + (long long)(n0 + r) * ldb + kt + kc);
                Bs[kc + 0][r] = tf32r(v.x);
                Bs[kc + 1][r] = tf32r(v.y);
                Bs[kc + 2][r] = tf32r(v.z);
                Bs[kc + 3][r] = tf32r(v.w);
            }
        } else {
            const int kr = t >> 4;                  // 0..15
            if (BN == 128) {
                const int n = (t & 15) * 8;
                const float4* p = reinterpret_cast<const float4*>(
                    Bb + (long long)(kt + kr) * ldb + n0 + n);
                float4 v0 = p[0], v1 = p[1];
                v0.x = tf32r(v0.x); v0.y = tf32r(v0.y);
                v0.z = tf32r(v0.z); v0.w = tf32r(v0.w);
                v1.x = tf32r(v1.x); v1.y = tf32r(v1.y);
                v1.z = tf32r(v1.z); v1.w = tf32r(v1.w);
                *reinterpret_cast<float4*>(&Bs[kr][n])     = v0;
                *reinterpret_cast<float4*>(&Bs[kr][n + 4]) = v1;
            } else {  // BN == 64
                const int n = (t & 15) * 4;
                float4 v = *reinterpret_cast<const float4*>(
                    Bb + (long long)(kt + kr) * ldb + n0 + n);
                v.x = tf32r(v.x); v.y = tf32r(v.y);
                v.z = tf32r(v.z); v.w = tf32r(v.w);
                *reinterpret_cast<float4*>(&Bs[kr][n]) = v;
            }
        }
        __syncthreads();

        // ---- two k-steps of 8 ----
        #pragma unroll
        for (int ks = 0; ks < TBK; ks += 8) {
            uint32_t af[M_AT][4];
            uint32_t bf[N_AT][2];
            #pragma unroll
            for (int ma = 0; ma < M_AT; ma++) {
                const int r = rb + ma * 16 + qr;
                af[ma][0] = __float_as_uint(As[ks + qc    ][r]);
                af[ma][1] = __float_as_uint(As[ks + qc    ][r + 8]);
                af[ma][2] = __float_as_uint(As[ks + qc + 4][r]);
                af[ma][3] = __float_as_uint(As[ks + qc + 4][r + 8]);
            }
            #pragma unroll
            for (int na = 0; na < N_AT; na++) {
                const int n = nb + na * 8 + qr;
                bf[na][0] = __float_as_uint(Bs[ks + qc    ][n]);
                bf[na][1] = __float_as_uint(Bs[ks + qc + 4][n]);
            }
            #pragma unroll
            for (int ma = 0; ma < M_AT; ma++)
                #pragma unroll
                for (int na = 0; na < N_AT; na++)
                    MMA_TF32(acc[ma][na], af[ma], bf[na]);
        }
        __syncthreads();
    }

    // ---- epilogue ----
    #pragma unroll
    for (int ma = 0; ma < M_AT; ma++) {
        const int row0 = m0 + rb + ma * 16 + qr;
        #pragma unroll
        for (int na = 0; na < N_AT; na++) {
            const int col0 = n0 + nb + na * 8 + qc * 2;
            float b0 = 0.f, b1 = 0.f;
            if (bias) { b0 = bias[col0]; b1 = bias[col0 + 1]; }
            float2 v0 = make_float2(acc[ma][na][0] * alpha + b0,
                                    acc[ma][na][1] * alpha + b1);
            float2 v1 = make_float2(acc[ma][na][2] * alpha + b0,
                                    acc[ma][na][3] * alpha + b1);
            *reinterpret_cast<float2*>(Cb + (long long)row0 * ldc + col0)       = v0;
            *reinterpret_cast<float2*>(Cb + (long long)(row0 + 8) * ldc + col0) = v1;
        }
    }
}

// ---------------- LayerNorm (+optional modulation) ----------------
__global__ __launch_bounds__(256)
void ln_kernel(const float* __restrict__ x, float* __restrict__ out,
               const float* __restrict__ gamma, const float* __restrict__ beta,
               int gstride, float add_one)
{
    const int row = blockIdx.x;          // b*L + l
    const int b   = row / LL;
    const float* px = x + (long long)row * CC;
    float*       po = out + (long long)row * CC;
    const int t = threadIdx.x;

    float v[4];
    float s = 0.f, s2 = 0.f;
    #pragma unroll
    for (int i = 0; i < 4; i++) {
        v[i] = px[t + i * 256];
        s  += v[i];
        s2 += v[i] * v[i];
    }
    __shared__ float sred[2][8];
    #pragma unroll
    for (int o = 16; o; o >>= 1) {
        s  += __shfl_xor_sync(0xffffffffu, s,  o);
        s2 += __shfl_xor_sync(0xffffffffu, s2, o);
    }
    if ((t & 31) == 0) { sred[0][t >> 5] = s; sred[1][t >> 5] = s2; }
    __syncthreads();
    s = 0.f; s2 = 0.f;
    #pragma unroll
    for (int w = 0; w < 8; w++) { s += sred[0][w]; s2 += sred[1][w]; }

    const float mu  = s * (1.f / CC);
    const float var = s2 * (1.f / CC) - mu * mu;
    const float r   = rsqrtf(var + EPS);

    const float* g  = gamma + (long long)b * gstride;
    const float* be = beta  + (long long)b * gstride;
    #pragma unroll
    for (int i = 0; i < 4; i++) {
        int c = t + i * 256;
        po[c] = (v[i] - mu) * r * (add_one + g[c]) + be[c];
    }
}

// ---------------- row softmax (in place), len = NPT*256 ----------------
template<int NPT>
__global__ __launch_bounds__(256)
void softmax_kernel(float* __restrict__ S)
{
    const int len = NPT * 256;
    float* p = S + (long long)blockIdx.x * len;
    const int t = threadIdx.x;

    float v[NPT];
    float mx = -1e30f;
    #pragma unroll
    for (int i = 0; i < NPT; i++) { v[i] = p[t + i * 256]; mx = fmaxf(mx, v[i]); }

    __shared__ float sred[8];
    #pragma unroll
    for (int o = 16; o; o >>= 1) mx = fmaxf(mx, __shfl_xor_sync(0xffffffffu, mx, o));
    if ((t & 31) == 0) sred[t >> 5] = mx;
    __syncthreads();
    float bm = sred[0];
    #pragma unroll
    for (int w = 1; w < 8; w++) bm = fmaxf(bm, sred[w]);
    __syncthreads();

    float s = 0.f;
    #pragma unroll
    for (int i = 0; i < NPT; i++) { v[i] = __expf(v[i] - bm); s += v[i]; }
    #pragma unroll
    for (int o = 16; o; o >>= 1) s += __shfl_xor_sync(0xffffffffu, s, o);
    if ((t & 31) == 0) sred[t >> 5] = s;
    __syncthreads();
    float bs = 0.f;
    #pragma unroll
    for (int w = 0; w < 8; w++) bs += sred[w];

    const float inv = 1.f / bs;
    #pragma unroll
    for (int i = 0; i < NPT; i++) p[t + i * 256] = v[i] * inv;
}

// ---------------- residual (+ optional per-(b,c) gate) ----------------
__global__ __launch_bounds__(256)
void residual_kernel(const float* __restrict__ base, const float* __restrict__ tt,
                     const float* __restrict__ gate, int gstride,
                     float* __restrict__ out)
{
    long long i = (long long)blockIdx.x * 256 + threadIdx.x;
    float g = 1.f;
    if (gate) {
        int b = (int)(i >> 21);        // L*C = 2^21
        int c = (int)(i & 1023);       // C   = 2^10
        g = gate[b * gstride + c];
    }
    out[i] = base[i] + tt[i] * g;
}

// ---------------- exact GELU ----------------
__global__ __launch_bounds__(256)
void gelu_kernel(float* __restrict__ p)
{
    long long i = (long long)blockIdx.x * 256 + threadIdx.x;
    float x = p[i];
    p[i] = 0.5f * x * (1.f + erff(x * 0.70710678118654752f));
}

// ---------------- adaLN: ada = silu(mod) @ w_ada + b_ada ----------------
__global__ __launch_bounds__(256)
void ada_kernel(const float* __restrict__ mod, const float* __restrict__ w,
                const float* __restrict__ bias, float* __restrict__ ada)
{
    __shared__ float sm[CC];
    const int b = blockIdx.y;
    const int j = blockIdx.x * 256 + threadIdx.x;   // 0..6143
    #pragma unroll
    for (int i = 0; i < 4; i++) {
        int c = threadIdx.x + i * 256;
        float m = mod[b * CC + c];
        sm[c] = m / (1.f + expf(-m));
    }
    __syncthreads();
    float acc = 0.f;
    for (int c = 0; c < CC; c++)
        acc = fmaf(sm[c], w[(long long)c * SIXC + j], acc);
    ada[(long long)b * SIXC + j] = acc + bias[j];
}

// ---------------- launch ----------------
extern "C" void kernel_launch(void* const* d_in, const int* in_sizes, int n_in,
                              void* d_out, int out_size)
{
    const float* x      = (const float*)d_in[0];
    const float* mod    = (const float*)d_in[1];
    const float* ctx    = (const float*)d_in[2];
    const float* w_ada  = (const float*)d_in[3];
    const float* b_ada  = (const float*)d_in[4];
    const float* w_qkv  = (const float*)d_in[5];
    const float* b_qkv  = (const float*)d_in[6];
    const float* w_so   = (const float*)d_in[7];
    const float* b_so   = (const float*)d_in[8];
    const float* gn2    = (const float*)d_in[9];
    const float* bn2    = (const float*)d_in[10];
    const float* w_cq   = (const float*)d_in[11];
    const float* b_cq   = (const float*)d_in[12];
    const float* w_ckv  = (const float*)d_in[13];
    const float* b_ckv  = (const float*)d_in[14];
    const float* w_co   = (const float*)d_in[15];
    const float* b_co   = (const float*)d_in[16];
    const float* w_m1   = (const float*)d_in[17];
    const float* b_m1   = (const float*)d_in[18];
    const float* w_m2   = (const float*)d_in[19];
    const float* b_m2   = (const float*)d_in[20];
    float* out = (float*)d_out;

    float *ph, *pqkv, *pS, *pO, *pt, *pkv, *pada;
    cudaGetSymbolAddress((void**)&ph,   g_h);
    cudaGetSymbolAddress((void**)&pqkv, g_qkv);
    cudaGetSymbolAddress((void**)&pS,   g_S);
    cudaGetSymbolAddress((void**)&pO,   g_O);
    cudaGetSymbolAddress((void**)&pt,   g_t);
    cudaGetSymbolAddress((void**)&pkv,  g_kv);
    cudaGetSymbolAddress((void**)&pada, g_ada);

    const long long totalBLC = (long long)MT * CC;      // 8,388,608
    const int resGrid  = (int)(totalBLC / 256);
    const int geluGrid = (int)(((long long)MT * 4 * CC) / 256);

    // 1. adaLN modulation
    ada_kernel<<<dim3(SIXC / 256, BB), 256>>>(mod, w_ada, b_ada, pada);

    // ===== MSA branch =====
    // h = LN(x)*(1+sc_msa) + sh_msa    (sc at +C, sh at +0, per-batch stride 6C)
    ln_kernel<<<MT, 256>>>(x, ph, pada + CC, pada, SIXC, 1.f);
    // qkv = h @ w_qkv + b_qkv
    tgemm_kernel<0, 128><<<dim3(3 * CC / 128, MT / TBM, 1), 256>>>(
        ph, w_qkv, b_qkv, pqkv, MT, 3 * CC, CC, CC, 3 * CC, 3 * CC, 0, 0, 0, 1.f);

    for (int b = 0; b < BB; b++) {
        const float* qb = pqkv + (long long)b * LL * 3 * CC;
        // S = Q K^T * scale   (batched over 16 heads)
        tgemm_kernel<1, 128><<<dim3(LL / 128, LL / TBM, HH), 256>>>(
            qb, qb + CC, nullptr, pS,
            LL, LL, DD, 3 * CC, 3 * CC, LL,
            DD, DD, (long long)LL * LL, ATT_SCALE);
        softmax_kernel<8><<<HH * LL, 256>>>(pS);
        // O = P V   (N=64 -> BN=64 instantiation)
        tgemm_kernel<0, 64><<<dim3(1, LL / TBM, HH), 256>>>(
            pS, qb + 2 * CC, nullptr, pO + (long long)b * LL * CC,
            LL, DD, LL, LL, 3 * CC, CC,
            (long long)LL * LL, DD, DD, 1.f);
    }
    // t = O @ w_so + b_so
    tgemm_kernel<0, 128><<<dim3(CC / 128, MT / TBM, 1), 256>>>(
        pO, w_so, b_so, pt, MT, CC, CC, CC, CC, CC, 0, 0, 0, 1.f);
    // x1 = x + t * g_msa   (gate at +2C)
    residual_kernel<<<resGrid, 256>>>(x, pt, pada + 2 * CC, SIXC, out);

    // ===== MCA branch =====
    // h = LN(x1) * g_n2 + b_n2
    ln_kernel<<<MT, 256>>>(out, ph, gn2, bn2, 0, 0.f);
    // q2 = h @ w_cq + b_cq  (reuse g_qkv)
    tgemm_kernel<0, 128><<<dim3(CC / 128, MT / TBM, 1), 256>>>(
        ph, w_cq, b_cq, pqkv, MT, CC, CC, CC, CC, CC, 0, 0, 0, 1.f);
    // kv = context @ w_ckv + b_ckv
    tgemm_kernel<0, 128><<<dim3(2 * CC / 128, (BB * LCC) / TBM, 1), 256>>>(
        ctx, w_ckv, b_ckv, pkv, BB * LCC, 2 * CC, CTXC, CTXC, 2 * CC, 2 * CC, 0, 0, 0, 1.f);

    for (int b = 0; b < BB; b++) {
        const float* q2b = pqkv + (long long)b * LL * CC;
        const float* kvb = pkv + (long long)b * LCC * 2 * CC;
        tgemm_kernel<1, 128><<<dim3(LCC / 128, LL / TBM, HH), 256>>>(
            q2b, kvb, nullptr, pS,
            LL, LCC, DD, CC, 2 * CC, LCC,
            DD, DD, (long long)LL * LCC, ATT_SCALE);
        softmax_kernel<2><<<HH * LL, 256>>>(pS);
        tgemm_kernel<0, 64><<<dim3(1, LL / TBM, HH), 256>>>(
            pS, kvb + CC, nullptr, pO + (long long)b * LL * CC,
            LL, DD, LCC, LCC, 2 * CC, CC,
            (long long)LL * LCC, DD, DD, 1.f);
    }
    // t = O @ w_co + b_co
    tgemm_kernel<0, 128><<<dim3(CC / 128, MT / TBM, 1), 256>>>(
        pO, w_co, b_co, pt, MT, CC, CC, CC, CC, CC, 0, 0, 0, 1.f);
    // x2 = x1 + t
    residual_kernel<<<resGrid, 256>>>(out, pt, nullptr, 0, out);

    // ===== FFN branch =====
    // h = LN(x2)*(1+sc_mlp) + sh_mlp   (sc at +4C, sh at +3C)
    ln_kernel<<<MT, 256>>>(out, ph, pada + 4 * CC, pada + 3 * CC, SIXC, 1.f);
    // m = h @ w_m1 + b_m1   (into g_S scratch, 134MB < 268MB)
    tgemm_kernel<0, 128><<<dim3(4 * CC / 128, MT / TBM, 1), 256>>>(
        ph, w_m1, b_m1, pS, MT, 4 * CC, CC, CC, 4 * CC, 4 * CC, 0, 0, 0, 1.f);
    gelu_kernel<<<geluGrid, 256>>>(pS);
    // t = m @ w_m2 + b_m2
    tgemm_kernel<0, 128><<<dim3(CC / 128, MT / TBM, 1), 256>>>(
        pS, w_m2, b_m2, pt, MT, CC, 4 * CC, 4 * CC, CC, CC, 0, 0, 0, 1.f);
    // x3 = x2 + t * g_mlp   (gate at +5C)
    residual_kernel<<<resGrid, 256>>>(out, pt, pada + 5 * CC, SIXC, out);
}

// round 3
// speedup vs baseline: 3.5444x; 1.1357x over previous
#include <cuda_runtime.h>
#include <cuda_bf16.h>
#include <math.h>
#include <stdint.h>

// ---------------- problem constants ----------------
#define BB   4
#define LL   2048
#define LCC  512
#define CC   1024
#define CTXC 1024
#define HH   16
#define DD   64
#define SIXC (6*CC)
#define MT   (BB*LL)          // 8192 token rows
#define EPS  1e-6f
#define ATT_SCALE 0.125f      // 1/sqrt(64)

// ---------------- device scratch (no allocations allowed) ----------------
__device__ float g_h  [(long long)MT * CC];        // LN outputs
__device__ float g_qkv[(long long)MT * 3 * CC];    // qkv / q2 reuse
__device__ float g_S  [(long long)HH * LL * LL];   // scores / FFN mid
__device__ float g_O  [(long long)MT * CC];        // attention output
__device__ float g_t  [(long long)MT * CC];        // projection temp
__device__ float g_kv [(long long)BB * LCC * 2 * CC]; // cross kv
__device__ float g_ada[(long long)BB * SIXC];      // modulation

// ---------------- async copy helpers ----------------
__device__ __forceinline__ void cp_async16(void* smem, const void* gmem) {
    uint32_t s = (uint32_t)__cvta_generic_to_shared(smem);
    asm volatile("cp.async.cg.shared.global [%0], [%1], 16;\n" :: "r"(s), "l"(gmem));
}
#define CP_COMMIT() asm volatile("cp.async.commit_group;\n" ::: "memory")
#define CP_WAIT1()  asm volatile("cp.async.wait_group 1;\n" ::: "memory")

#define MMA_TF32(d, a, b)                                                     \
    asm volatile("mma.sync.aligned.m16n8k8.row.col.f32.tf32.tf32.f32 "        \
                 "{%0,%1,%2,%3}, {%4,%5,%6,%7}, {%8,%9}, {%0,%1,%2,%3};\n"    \
                 : "+f"((d)[0]), "+f"((d)[1]), "+f"((d)[2]), "+f"((d)[3])     \
                 : "r"((a)[0]), "r"((a)[1]), "r"((a)[2]), "r"((a)[3]),        \
                   "r"((b)[0]), "r"((b)[1]))

__device__ __forceinline__ float gelu_exact(float x) {
    return 0.5f * x * (1.f + erff(x * 0.70710678118654752f));
}

// ---------------- generic batched tf32 tensor-core GEMM (cp.async pipelined) ----------------
// C[z] = act(alpha * A[z] (MxK, row-major) * B[z] (KxN; TRANSB: stored NxK) + bias)
// Requirements (all call sites satisfy): M % 128 == 0, N % BN == 0, K % 16 == 0,
// leading dims % 4 == 0, 16B-aligned base pointers.
#define TBM 128
#define TBK 16

template<int TRANSB, int BN, int ACT>
__global__ __launch_bounds__(256, 2)
void tgemm_kernel(const float* __restrict__ A, const float* __restrict__ Bp,
                  const float* __restrict__ bias, float* __restrict__ Cp,
                  int M, int N, int K, int lda, int ldb, int ldc,
                  long long strideA, long long strideB, long long strideC,
                  float alpha)
{
    constexpr int AST  = 20;        // A row stride (floats): 20 % 32 pattern -> conflict-free frags
    constexpr int BSTT = 20;        // trans-B row stride
    constexpr int BSTN = BN + 4;    // NN-B row stride (== 4 mod 32 -> conflict-free frags)
    constexpr int BS_ELEMS = TRANSB ? (BN * BSTT) : (TBK * BSTN);

    __shared__ float As[2][TBM * AST];
    __shared__ float Bs[2][BS_ELEMS];

    constexpr int WARPS_N = BN / 32;          // 4 (BN=128) or 2 (BN=64)
    constexpr int WARPS_M = 8 / WARPS_N;      // 2 or 4
    constexpr int WM = TBM / WARPS_M;         // 64 or 32
    constexpr int M_AT = WM / 16;             // 4 or 2
    constexpr int N_AT = 4;                   // 32 / 8

    const int z = blockIdx.z;
    const float* Ab = A  + (long long)z * strideA;
    const float* Bb = Bp + (long long)z * strideB;
    float*       Cb = Cp + (long long)z * strideC;

    const int t    = threadIdx.x;
    const int m0   = blockIdx.y * TBM;
    const int n0   = blockIdx.x * BN;
    const int lane = t & 31;
    const int warp = t >> 5;
    const int qr   = lane >> 2;   // 0..7
    const int qc   = lane & 3;    // 0..3
    const int wm   = warp / WARPS_N;
    const int wn   = warp % WARPS_N;
    const int rb   = wm * WM;     // warp m-base in tile
    const int nb   = wn * 32;     // warp n-base in tile

    float acc[M_AT][N_AT][4];
    #pragma unroll
    for (int i = 0; i < M_AT; i++)
        #pragma unroll
        for (int j = 0; j < N_AT; j++)
            #pragma unroll
            for (int r = 0; r < 4; r++) acc[i][j][r] = 0.f;

    const int a_r  = t >> 1;            // 0..127
    const int a_kc = (t & 1) * 8;       // 0 or 8

    auto load_tiles = [&](int kt, int st) {
        // A tile: 128 x 16
        {
            const float* ga = Ab + (long long)(m0 + a_r) * lda + kt + a_kc;
            float* sa = &As[st][a_r * AST + a_kc];
            cp_async16(sa,     ga);
            cp_async16(sa + 4, ga + 4);
        }
        if (TRANSB) {
            if (BN == 128) {
                const int r = t >> 1, kc = (t & 1) * 8;
                const float* gb = Bb + (long long)(n0 + r) * ldb + kt + kc;
                float* sb = &Bs[st][r * BSTT + kc];
                cp_async16(sb,     gb);
                cp_async16(sb + 4, gb + 4);
            } else {  // BN == 64
                const int r = t >> 2, kc = (t & 3) * 4;
                const float* gb = Bb + (long long)(n0 + r) * ldb + kt + kc;
                cp_async16(&Bs[st][r * BSTT + kc], gb);
            }
        } else {
            const int kr = t >> 4;      // 0..15
            if (BN == 128) {
                const int n = (t & 15) * 8;
                const float* gb = Bb + (long long)(kt + kr) * ldb + n0 + n;
                float* sb = &Bs[st][kr * BSTN + n];
                cp_async16(sb,     gb);
                cp_async16(sb + 4, gb + 4);
            } else {  // BN == 64
                const int n = (t & 15) * 4;
                const float* gb = Bb + (long long)(kt + kr) * ldb + n0 + n;
                cp_async16(&Bs[st][kr * BSTN + n], gb);
            }
        }
    };

    load_tiles(0, 0);
    CP_COMMIT();

    int st = 0;
    for (int kt = 0; kt < K; kt += TBK) {
        if (kt + TBK < K) load_tiles(kt + TBK, st ^ 1);
        CP_COMMIT();
        CP_WAIT1();          // current stage's group complete
        __syncthreads();

        #pragma unroll
        for (int ks = 0; ks < TBK; ks += 8) {
            uint32_t af[M_AT][4];
            uint32_t bf[N_AT][2];
            #pragma unroll
            for (int ma = 0; ma < M_AT; ma++) {
                const int r = rb + ma * 16 + qr;
                af[ma][0] = __float_as_uint(As[st][r * AST + ks + qc]);
                af[ma][1] = __float_as_uint(As[st][(r + 8) * AST + ks + qc]);
                af[ma][2] = __float_as_uint(As[st][r * AST + ks + qc + 4]);
                af[ma][3] = __float_as_uint(As[st][(r + 8) * AST + ks + qc + 4]);
            }
            #pragma unroll
            for (int na = 0; na < N_AT; na++) {
                const int n = nb + na * 8 + qr;
                if (TRANSB) {
                    bf[na][0] = __float_as_uint(Bs[st][n * BSTT + ks + qc]);
                    bf[na][1] = __float_as_uint(Bs[st][n * BSTT + ks + qc + 4]);
                } else {
                    bf[na][0] = __float_as_uint(Bs[st][(ks + qc) * BSTN + n]);
                    bf[na][1] = __float_as_uint(Bs[st][(ks + qc + 4) * BSTN + n]);
                }
            }
            #pragma unroll
            for (int ma = 0; ma < M_AT; ma++)
                #pragma unroll
                for (int na = 0; na < N_AT; na++)
                    MMA_TF32(acc[ma][na], af[ma], bf[na]);
        }
        __syncthreads();
        st ^= 1;
    }

    // ---- epilogue ----
    #pragma unroll
    for (int ma = 0; ma < M_AT; ma++) {
        const int row0 = m0 + rb + ma * 16 + qr;
        #pragma unroll
        for (int na = 0; na < N_AT; na++) {
            const int col0 = n0 + nb + na * 8 + qc * 2;
            float b0 = 0.f, b1 = 0.f;
            if (bias) { b0 = bias[col0]; b1 = bias[col0 + 1]; }
            float v00 = acc[ma][na][0] * alpha + b0;
            float v01 = acc[ma][na][1] * alpha + b1;
            float v10 = acc[ma][na][2] * alpha + b0;
            float v11 = acc[ma][na][3] * alpha + b1;
            if (ACT == 1) {
                v00 = gelu_exact(v00); v01 = gelu_exact(v01);
                v10 = gelu_exact(v10); v11 = gelu_exact(v11);
            }
            *reinterpret_cast<float2*>(Cb + (long long)row0 * ldc + col0)       = make_float2(v00, v01);
            *reinterpret_cast<float2*>(Cb + (long long)(row0 + 8) * ldc + col0) = make_float2(v10, v11);
        }
    }
}

// ---------------- LayerNorm (+optional modulation) ----------------
__global__ __launch_bounds__(256)
void ln_kernel(const float* __restrict__ x, float* __restrict__ out,
               const float* __restrict__ gamma, const float* __restrict__ beta,
               int gstride, float add_one)
{
    const int row = blockIdx.x;          // b*L + l
    const int b   = row / LL;
    const float* px = x + (long long)row * CC;
    float*       po = out + (long long)row * CC;
    const int t = threadIdx.x;

    float v[4];
    float s = 0.f, s2 = 0.f;
    #pragma unroll
    for (int i = 0; i < 4; i++) {
        v[i] = px[t + i * 256];
        s  += v[i];
        s2 += v[i] * v[i];
    }
    __shared__ float sred[2][8];
    #pragma unroll
    for (int o = 16; o; o >>= 1) {
        s  += __shfl_xor_sync(0xffffffffu, s,  o);
        s2 += __shfl_xor_sync(0xffffffffu, s2, o);
    }
    if ((t & 31) == 0) { sred[0][t >> 5] = s; sred[1][t >> 5] = s2; }
    __syncthreads();
    s = 0.f; s2 = 0.f;
    #pragma unroll
    for (int w = 0; w < 8; w++) { s += sred[0][w]; s2 += sred[1][w]; }

    const float mu  = s * (1.f / CC);
    const float var = s2 * (1.f / CC) - mu * mu;
    const float r   = rsqrtf(var + EPS);

    const float* g  = gamma + (long long)b * gstride;
    const float* be = beta  + (long long)b * gstride;
    #pragma unroll
    for (int i = 0; i < 4; i++) {
        int c = t + i * 256;
        po[c] = (v[i] - mu) * r * (add_one + g[c]) + be[c];
    }
}

// ---------------- row softmax (in place), len = NPT*256 ----------------
template<int NPT>
__global__ __launch_bounds__(256)
void softmax_kernel(float* __restrict__ S)
{
    const int len = NPT * 256;
    float* p = S + (long long)blockIdx.x * len;
    const int t = threadIdx.x;

    float v[NPT];
    float mx = -1e30f;
    #pragma unroll
    for (int i = 0; i < NPT; i++) { v[i] = p[t + i * 256]; mx = fmaxf(mx, v[i]); }

    __shared__ float sred[8];
    #pragma unroll
    for (int o = 16; o; o >>= 1) mx = fmaxf(mx, __shfl_xor_sync(0xffffffffu, mx, o));
    if ((t & 31) == 0) sred[t >> 5] = mx;
    __syncthreads();
    float bm = sred[0];
    #pragma unroll
    for (int w = 1; w < 8; w++) bm = fmaxf(bm, sred[w]);
    __syncthreads();

    float s = 0.f;
    #pragma unroll
    for (int i = 0; i < NPT; i++) { v[i] = __expf(v[i] - bm); s += v[i]; }
    #pragma unroll
    for (int o = 16; o; o >>= 1) s += __shfl_xor_sync(0xffffffffu, s, o);
    if ((t & 31) == 0) sred[t >> 5] = s;
    __syncthreads();
    float bs = 0.f;
    #pragma unroll
    for (int w = 0; w < 8; w++) bs += sred[w];

    const float inv = 1.f / bs;
    #pragma unroll
    for (int i = 0; i < NPT; i++) p[t + i * 256] = v[i] * inv;
}

// ---------------- residual (+ optional per-(b,c) gate) ----------------
__global__ __launch_bounds__(256)
void residual_kernel(const float* __restrict__ base, const float* __restrict__ tt,
                     const float* __restrict__ gate, int gstride,
                     float* __restrict__ out)
{
    long long i = (long long)blockIdx.x * 256 + threadIdx.x;
    float g = 1.f;
    if (gate) {
        int b = (int)(i >> 21);        // L*C = 2^21
        int c = (int)(i & 1023);       // C   = 2^10
        g = gate[b * gstride + c];
    }
    out[i] = base[i] + tt[i] * g;
}

// ---------------- adaLN: ada = silu(mod) @ w_ada + b_ada ----------------
__global__ __launch_bounds__(256)
void ada_kernel(const float* __restrict__ mod, const float* __restrict__ w,
                const float* __restrict__ bias, float* __restrict__ ada)
{
    __shared__ float sm[CC];
    const int b = blockIdx.y;
    const int j = blockIdx.x * 256 + threadIdx.x;   // 0..6143
    #pragma unroll
    for (int i = 0; i < 4; i++) {
        int c = threadIdx.x + i * 256;
        float m = mod[b * CC + c];
        sm[c] = m / (1.f + expf(-m));
    }
    __syncthreads();
    float acc = 0.f;
    for (int c = 0; c < CC; c++)
        acc = fmaf(sm[c], w[(long long)c * SIXC + j], acc);
    ada[(long long)b * SIXC + j] = acc + bias[j];
}

// ---------------- launch ----------------
extern "C" void kernel_launch(void* const* d_in, const int* in_sizes, int n_in,
                              void* d_out, int out_size)
{
    const float* x      = (const float*)d_in[0];
    const float* mod    = (const float*)d_in[1];
    const float* ctx    = (const float*)d_in[2];
    const float* w_ada  = (const float*)d_in[3];
    const float* b_ada  = (const float*)d_in[4];
    const float* w_qkv  = (const float*)d_in[5];
    const float* b_qkv  = (const float*)d_in[6];
    const float* w_so   = (const float*)d_in[7];
    const float* b_so   = (const float*)d_in[8];
    const float* gn2    = (const float*)d_in[9];
    const float* bn2    = (const float*)d_in[10];
    const float* w_cq   = (const float*)d_in[11];
    const float* b_cq   = (const float*)d_in[12];
    const float* w_ckv  = (const float*)d_in[13];
    const float* b_ckv  = (const float*)d_in[14];
    const float* w_co   = (const float*)d_in[15];
    const float* b_co   = (const float*)d_in[16];
    const float* w_m1   = (const float*)d_in[17];
    const float* b_m1   = (const float*)d_in[18];
    const float* w_m2   = (const float*)d_in[19];
    const float* b_m2   = (const float*)d_in[20];
    float* out = (float*)d_out;

    float *ph, *pqkv, *pS, *pO, *pt, *pkv, *pada;
    cudaGetSymbolAddress((void**)&ph,   g_h);
    cudaGetSymbolAddress((void**)&pqkv, g_qkv);
    cudaGetSymbolAddress((void**)&pS,   g_S);
    cudaGetSymbolAddress((void**)&pO,   g_O);
    cudaGetSymbolAddress((void**)&pt,   g_t);
    cudaGetSymbolAddress((void**)&pkv,  g_kv);
    cudaGetSymbolAddress((void**)&pada, g_ada);

    const long long totalBLC = (long long)MT * CC;      // 8,388,608
    const int resGrid  = (int)(totalBLC / 256);

    // 1. adaLN modulation
    ada_kernel<<<dim3(SIXC / 256, BB), 256>>>(mod, w_ada, b_ada, pada);

    // ===== MSA branch =====
    ln_kernel<<<MT, 256>>>(x, ph, pada + CC, pada, SIXC, 1.f);
    tgemm_kernel<0, 128, 0><<<dim3(3 * CC / 128, MT / TBM, 1), 256>>>(
        ph, w_qkv, b_qkv, pqkv, MT, 3 * CC, CC, CC, 3 * CC, 3 * CC, 0, 0, 0, 1.f);

    for (int b = 0; b < BB; b++) {
        const float* qb = pqkv + (long long)b * LL * 3 * CC;
        tgemm_kernel<1, 128, 0><<<dim3(LL / 128, LL / TBM, HH), 256>>>(
            qb, qb + CC, nullptr, pS,
            LL, LL, DD, 3 * CC, 3 * CC, LL,
            DD, DD, (long long)LL * LL, ATT_SCALE);
        softmax_kernel<8><<<HH * LL, 256>>>(pS);
        tgemm_kernel<0, 64, 0><<<dim3(1, LL / TBM, HH), 256>>>(
            pS, qb + 2 * CC, nullptr, pO + (long long)b * LL * CC,
            LL, DD, LL, LL, 3 * CC, CC,
            (long long)LL * LL, DD, DD, 1.f);
    }
    tgemm_kernel<0, 128, 0><<<dim3(CC / 128, MT / TBM, 1), 256>>>(
        pO, w_so, b_so, pt, MT, CC, CC, CC, CC, CC, 0, 0, 0, 1.f);
    residual_kernel<<<resGrid, 256>>>(x, pt, pada + 2 * CC, SIXC, out);

    // ===== MCA branch =====
    ln_kernel<<<MT, 256>>>(out, ph, gn2, bn2, 0, 0.f);
    tgemm_kernel<0, 128, 0><<<dim3(CC / 128, MT / TBM, 1), 256>>>(
        ph, w_cq, b_cq, pqkv, MT, CC, CC, CC, CC, CC, 0, 0, 0, 1.f);
    tgemm_kernel<0, 128, 0><<<dim3(2 * CC / 128, (BB * LCC) / TBM, 1), 256>>>(
        ctx, w_ckv, b_ckv, pkv, BB * LCC, 2 * CC, CTXC, CTXC, 2 * CC, 2 * CC, 0, 0, 0, 1.f);

    for (int b = 0; b < BB; b++) {
        const float* q2b = pqkv + (long long)b * LL * CC;
        const float* kvb = pkv + (long long)b * LCC * 2 * CC;
        tgemm_kernel<1, 128, 0><<<dim3(LCC / 128, LL / TBM, HH), 256>>>(
            q2b, kvb, nullptr, pS,
            LL, LCC, DD, CC, 2 * CC, LCC,
            DD, DD, (long long)LL * LCC, ATT_SCALE);
        softmax_kernel<2><<<HH * LL, 256>>>(pS);
        tgemm_kernel<0, 64, 0><<<dim3(1, LL / TBM, HH), 256>>>(
            pS, kvb + CC, nullptr, pO + (long long)b * LL * CC,
            LL, DD, LCC, LCC, 2 * CC, CC,
            (long long)LL * LCC, DD, DD, 1.f);
    }
    tgemm_kernel<0, 128, 0><<<dim3(CC / 128, MT / TBM, 1), 256>>>(
        pO, w_co, b_co, pt, MT, CC, CC, CC, CC, CC, 0, 0, 0, 1.f);
    residual_kernel<<<resGrid, 256>>>(out, pt, nullptr, 0, out);

    // ===== FFN branch =====
    ln_kernel<<<MT, 256>>>(out, ph, pada + 4 * CC, pada + 3 * CC, SIXC, 1.f);
    // m = gelu(h @ w_m1 + b_m1)  — GELU fused into epilogue
    tgemm_kernel<0, 128, 1><<<dim3(4 * CC / 128, MT / TBM, 1), 256>>>(
        ph, w_m1, b_m1, pS, MT, 4 * CC, CC, CC, 4 * CC, 4 * CC, 0, 0, 0, 1.f);
    tgemm_kernel<0, 128, 0><<<dim3(CC / 128, MT / TBM, 1), 256>>>(
        pS, w_m2, b_m2, pt, MT, CC, 4 * CC, 4 * CC, CC, CC, 0, 0, 0, 1.f);
    residual_kernel<<<resGrid, 256>>>(out, pt, pada + 5 * CC, SIXC, out);
}

// round 4
// speedup vs baseline: 4.6778x; 1.3198x over previous
#include <cuda_runtime.h>
#include <cuda_bf16.h>
#include <math.h>
#include <stdint.h>

// ---------------- problem constants ----------------
#define BB   4
#define LL   2048
#define LCC  512
#define CC   1024
#define CTXC 1024
#define HH   16
#define DD   64
#define SIXC (6*CC)
#define MT   (BB*LL)          // 8192 token rows
#define EPS  1e-6f
#define ATT_SCALE 0.125f      // 1/sqrt(64)

// ---------------- device scratch (no allocations allowed) ----------------
__device__ float g_h  [(long long)MT * CC];        // LN outputs
__device__ float g_qkv[(long long)MT * 3 * CC];    // qkv / q2 reuse
__device__ float g_S  [(long long)MT * 4 * CC];    // FFN mid
__device__ float g_O  [(long long)MT * CC];        // attention output
__device__ float g_t  [(long long)MT * CC];        // projection temp
__device__ float g_kv [(long long)BB * LCC * 2 * CC]; // cross kv
__device__ float g_ada[(long long)BB * SIXC];      // modulation

// ---------------- async copy helpers ----------------
__device__ __forceinline__ void cp_async16(void* smem, const void* gmem) {
    uint32_t s = (uint32_t)__cvta_generic_to_shared(smem);
    asm volatile("cp.async.cg.shared.global [%0], [%1], 16;\n" :: "r"(s), "l"(gmem));
}
#define CP_COMMIT() asm volatile("cp.async.commit_group;\n" ::: "memory")
#define CP_WAIT1()  asm volatile("cp.async.wait_group 1;\n" ::: "memory")

#define MMA_TF32(d, a, b)                                                     \
    asm volatile("mma.sync.aligned.m16n8k8.row.col.f32.tf32.tf32.f32 "        \
                 "{%0,%1,%2,%3}, {%4,%5,%6,%7}, {%8,%9}, {%0,%1,%2,%3};\n"    \
                 : "+f"((d)[0]), "+f"((d)[1]), "+f"((d)[2]), "+f"((d)[3])     \
                 : "r"((a)[0]), "r"((a)[1]), "r"((a)[2]), "r"((a)[3]),        \
                   "r"((b)[0]), "r"((b)[1]))

__device__ __forceinline__ float gelu_exact(float x) {
    return 0.5f * x * (1.f + erff(x * 0.70710678118654752f));
}

// ---------------- generic batched tf32 tensor-core GEMM (cp.async pipelined) ----------------
#define TBM 128
#define TBK 16

template<int TRANSB, int BN, int ACT>
__global__ __launch_bounds__(256, 2)
void tgemm_kernel(const float* __restrict__ A, const float* __restrict__ Bp,
                  const float* __restrict__ bias, float* __restrict__ Cp,
                  int M, int N, int K, int lda, int ldb, int ldc,
                  long long strideA, long long strideB, long long strideC,
                  float alpha)
{
    constexpr int AST  = 20;        // A row stride (floats)
    constexpr int BSTT = 20;        // trans-B row stride
    constexpr int BSTN = BN + 8;    // NN-B row stride (== 8 mod 32 -> conflict-free frags)
    constexpr int BS_ELEMS = TRANSB ? (BN * BSTT) : (TBK * BSTN);

    __shared__ float As[2][TBM * AST];
    __shared__ float Bs[2][BS_ELEMS];

    constexpr int WARPS_N = BN / 32;
    constexpr int WARPS_M = 8 / WARPS_N;
    constexpr int WM = TBM / WARPS_M;
    constexpr int M_AT = WM / 16;
    constexpr int N_AT = 4;

    const int z = blockIdx.z;
    const float* Ab = A  + (long long)z * strideA;
    const float* Bb = Bp + (long long)z * strideB;
    float*       Cb = Cp + (long long)z * strideC;

    const int t    = threadIdx.x;
    const int m0   = blockIdx.y * TBM;
    const int n0   = blockIdx.x * BN;
    const int lane = t & 31;
    const int warp = t >> 5;
    const int qr   = lane >> 2;
    const int qc   = lane & 3;
    const int wm   = warp / WARPS_N;
    const int wn   = warp % WARPS_N;
    const int rb   = wm * WM;
    const int nb   = wn * 32;

    float acc[M_AT][N_AT][4];
    #pragma unroll
    for (int i = 0; i < M_AT; i++)
        #pragma unroll
        for (int j = 0; j < N_AT; j++)
            #pragma unroll
            for (int r = 0; r < 4; r++) acc[i][j][r] = 0.f;

    const int a_r  = t >> 1;
    const int a_kc = (t & 1) * 8;

    auto load_tiles = [&](int kt, int st) {
        {
            const float* ga = Ab + (long long)(m0 + a_r) * lda + kt + a_kc;
            float* sa = &As[st][a_r * AST + a_kc];
            cp_async16(sa,     ga);
            cp_async16(sa + 4, ga + 4);
        }
        if (TRANSB) {
            if (BN == 128) {
                const int r = t >> 1, kc = (t & 1) * 8;
                const float* gb = Bb + (long long)(n0 + r) * ldb + kt + kc;
                float* sb = &Bs[st][r * BSTT + kc];
                cp_async16(sb,     gb);
                cp_async16(sb + 4, gb + 4);
            } else {
                const int r = t >> 2, kc = (t & 3) * 4;
                const float* gb = Bb + (long long)(n0 + r) * ldb + kt + kc;
                cp_async16(&Bs[st][r * BSTT + kc], gb);
            }
        } else {
            const int kr = t >> 4;
            if (BN == 128) {
                const int n = (t & 15) * 8;
                const float* gb = Bb + (long long)(kt + kr) * ldb + n0 + n;
                float* sb = &Bs[st][kr * BSTN + n];
                cp_async16(sb,     gb);
                cp_async16(sb + 4, gb + 4);
            } else {
                const int n = (t & 15) * 4;
                const float* gb = Bb + (long long)(kt + kr) * ldb + n0 + n;
                cp_async16(&Bs[st][kr * BSTN + n], gb);
            }
        }
    };

    load_tiles(0, 0);
    CP_COMMIT();

    int st = 0;
    for (int kt = 0; kt < K; kt += TBK) {
        if (kt + TBK < K) load_tiles(kt + TBK, st ^ 1);
        CP_COMMIT();
        CP_WAIT1();
        __syncthreads();

        #pragma unroll
        for (int ks = 0; ks < TBK; ks += 8) {
            uint32_t af[M_AT][4];
            uint32_t bf[N_AT][2];
            #pragma unroll
            for (int ma = 0; ma < M_AT; ma++) {
                const int r = rb + ma * 16 + qr;
                af[ma][0] = __float_as_uint(As[st][r * AST + ks + qc]);
                af[ma][1] = __float_as_uint(As[st][(r + 8) * AST + ks + qc]);
                af[ma][2] = __float_as_uint(As[st][r * AST + ks + qc + 4]);
                af[ma][3] = __float_as_uint(As[st][(r + 8) * AST + ks + qc + 4]);
            }
            #pragma unroll
            for (int na = 0; na < N_AT; na++) {
                const int n = nb + na * 8 + qr;
                if (TRANSB) {
                    bf[na][0] = __float_as_uint(Bs[st][n * BSTT + ks + qc]);
                    bf[na][1] = __float_as_uint(Bs[st][n * BSTT + ks + qc + 4]);
                } else {
                    bf[na][0] = __float_as_uint(Bs[st][(ks + qc) * BSTN + n]);
                    bf[na][1] = __float_as_uint(Bs[st][(ks + qc + 4) * BSTN + n]);
                }
            }
            #pragma unroll
            for (int ma = 0; ma < M_AT; ma++)
                #pragma unroll
                for (int na = 0; na < N_AT; na++)
                    MMA_TF32(acc[ma][na], af[ma], bf[na]);
        }
        __syncthreads();
        st ^= 1;
    }

    #pragma unroll
    for (int ma = 0; ma < M_AT; ma++) {
        const int row0 = m0 + rb + ma * 16 + qr;
        #pragma unroll
        for (int na = 0; na < N_AT; na++) {
            const int col0 = n0 + nb + na * 8 + qc * 2;
            float b0 = 0.f, b1 = 0.f;
            if (bias) { b0 = bias[col0]; b1 = bias[col0 + 1]; }
            float v00 = acc[ma][na][0] * alpha + b0;
            float v01 = acc[ma][na][1] * alpha + b1;
            float v10 = acc[ma][na][2] * alpha + b0;
            float v11 = acc[ma][na][3] * alpha + b1;
            if (ACT == 1) {
                v00 = gelu_exact(v00); v01 = gelu_exact(v01);
                v10 = gelu_exact(v10); v11 = gelu_exact(v11);
            }
            *reinterpret_cast<float2*>(Cb + (long long)row0 * ldc + col0)       = make_float2(v00, v01);
            *reinterpret_cast<float2*>(Cb + (long long)(row0 + 8) * ldc + col0) = make_float2(v10, v11);
        }
    }
}

// ---------------- flash attention ----------------
// Per CTA: one (batch=z, head=y, 128-row Q tile=x). 8 warps x 16 rows.
// K/V tiles of 64 kv-positions, double-buffered via cp.async.
// smem: Q 128*68 | K 2*64*68 | V 2*64*72  = 106496 B
#define QST 68
#define KST 68
#define VST 72
#define FLASH_SMEM ((128*QST + 2*64*KST + 2*64*VST) * 4)

__global__ __launch_bounds__(256, 2)
void flash_kernel(const float* __restrict__ Qp, const float* __restrict__ Kp,
                  const float* __restrict__ Vp, float* __restrict__ Op,
                  int qld, int kld, int kvRows, int nkv)
{
    extern __shared__ float fsm[];
    float* Qs = fsm;                    // 128*QST
    float* Ks = Qs + 128 * QST;         // 2 stages of 64*KST (trans: [n][k])
    float* Vs = Ks + 2 * 64 * KST;      // 2 stages of 64*VST ([k][n])

    const int t    = threadIdx.x;
    const int lane = t & 31;
    const int warp = t >> 5;
    const int qr   = lane >> 2;
    const int qc   = lane & 3;

    const int b = blockIdx.z, h = blockIdx.y;
    const float* Qg = Qp + (long long)(b * LL + blockIdx.x * 128) * qld + h * DD;
    const float* Kg = Kp + (long long)b * kvRows * kld + h * DD;
    const float* Vg = Vp + (long long)b * kvRows * kld + h * DD;
    float*       Og = Op + (long long)(b * LL + blockIdx.x * 128) * CC + h * DD;

    // ---- load Q tile (group 0) ----
    {
        const int r = t >> 1, kc = (t & 1) * 32;
        const float* g = Qg + (long long)r * qld + kc;
        float* s = Qs + r * QST + kc;
        #pragma unroll
        for (int i = 0; i < 8; i++) cp_async16(s + i * 4, g + i * 4);
    }
    CP_COMMIT();

    auto load_kv = [&](int it, int st) {
        const int kv0 = it * 64;
        {   // K: trans layout Ks[n*KST + k]
            const int n = t >> 2, kc = (t & 3) * 16;
            const float* g = Kg + (long long)(kv0 + n) * kld + kc;
            float* s = Ks + st * (64 * KST) + n * KST + kc;
            cp_async16(s,      g);
            cp_async16(s + 4,  g + 4);
            cp_async16(s + 8,  g + 8);
            cp_async16(s + 12, g + 12);
        }
        {   // V: NN layout Vs[k*VST + n]
            const int k = t >> 2, nc = (t & 3) * 16;
            const float* g = Vg + (long long)(kv0 + k) * kld + nc;
            float* s = Vs + st * (64 * VST) + k * VST + nc;
            cp_async16(s,      g);
            cp_async16(s + 4,  g + 4);
            cp_async16(s + 8,  g + 8);
            cp_async16(s + 12, g + 12);
        }
    };

    load_kv(0, 0);
    CP_COMMIT();

    const int rw = warp * 16 + qr;      // this thread's low row within tile

    float o[8][4];
    #pragma unroll
    for (int na = 0; na < 8; na++)
        #pragma unroll
        for (int j = 0; j < 4; j++) o[na][j] = 0.f;
    float m_lo = -INFINITY, m_hi = -INFINITY;
    float l_lo = 0.f, l_hi = 0.f;

    int st = 0;
    for (int it = 0; it < nkv; it++) {
        if (it + 1 < nkv) load_kv(it + 1, st ^ 1);
        CP_COMMIT();
        CP_WAIT1();
        __syncthreads();

        const float* Kst = Ks + st * (64 * KST);
        const float* Vst = Vs + st * (64 * VST);

        // ---- S = Q K^T ----
        float sa[8][4];
        #pragma unroll
        for (int na = 0; na < 8; na++)
            #pragma unroll
            for (int j = 0; j < 4; j++) sa[na][j] = 0.f;

        #pragma unroll
        for (int ks = 0; ks < 8; ks++) {
            uint32_t af[4];
            af[0] = __float_as_uint(Qs[rw * QST + ks * 8 + qc]);
            af[1] = __float_as_uint(Qs[(rw + 8) * QST + ks * 8 + qc]);
            af[2] = __float_as_uint(Qs[rw * QST + ks * 8 + qc + 4]);
            af[3] = __float_as_uint(Qs[(rw + 8) * QST + ks * 8 + qc + 4]);
            #pragma unroll
            for (int na = 0; na < 8; na++) {
                uint32_t bf[2];
                bf[0] = __float_as_uint(Kst[(na * 8 + qr) * KST + ks * 8 + qc]);
                bf[1] = __float_as_uint(Kst[(na * 8 + qr) * KST + ks * 8 + qc + 4]);
                MMA_TF32(sa[na], af, bf);
            }
        }

        // ---- online softmax (rows qr -> lo, qr+8 -> hi) ----
        float tm_lo = -INFINITY, tm_hi = -INFINITY;
        #pragma unroll
        for (int na = 0; na < 8; na++) {
            sa[na][0] *= ATT_SCALE; sa[na][1] *= ATT_SCALE;
            sa[na][2] *= ATT_SCALE; sa[na][3] *= ATT_SCALE;
            tm_lo = fmaxf(tm_lo, fmaxf(sa[na][0], sa[na][1]));
            tm_hi = fmaxf(tm_hi, fmaxf(sa[na][2], sa[na][3]));
        }
        tm_lo = fmaxf(tm_lo, __shfl_xor_sync(0xffffffffu, tm_lo, 1));
        tm_lo = fmaxf(tm_lo, __shfl_xor_sync(0xffffffffu, tm_lo, 2));
        tm_hi = fmaxf(tm_hi, __shfl_xor_sync(0xffffffffu, tm_hi, 1));
        tm_hi = fmaxf(tm_hi, __shfl_xor_sync(0xffffffffu, tm_hi, 2));

        const float mn_lo = fmaxf(m_lo, tm_lo);
        const float mn_hi = fmaxf(m_hi, tm_hi);
        const float sc_lo = __expf(m_lo - mn_lo);
        const float sc_hi = __expf(m_hi - mn_hi);
        m_lo = mn_lo; m_hi = mn_hi;

        float rl = 0.f, rh = 0.f;
        #pragma unroll
        for (int na = 0; na < 8; na++) {
            sa[na][0] = __expf(sa[na][0] - mn_lo);
            sa[na][1] = __expf(sa[na][1] - mn_lo);
            sa[na][2] = __expf(sa[na][2] - mn_hi);
            sa[na][3] = __expf(sa[na][3] - mn_hi);
            rl += sa[na][0] + sa[na][1];
            rh += sa[na][2] + sa[na][3];
        }
        rl += __shfl_xor_sync(0xffffffffu, rl, 1);
        rl += __shfl_xor_sync(0xffffffffu, rl, 2);
        rh += __shfl_xor_sync(0xffffffffu, rh, 1);
        rh += __shfl_xor_sync(0xffffffffu, rh, 2);
        l_lo = l_lo * sc_lo + rl;
        l_hi = l_hi * sc_hi + rh;

        #pragma unroll
        for (int na = 0; na < 8; na++) {
            o[na][0] *= sc_lo; o[na][1] *= sc_lo;
            o[na][2] *= sc_hi; o[na][3] *= sc_hi;
        }

        // ---- O += P V  (A-frags gathered from sa via quad shuffles) ----
        const int srcA = (qr << 2) | (qc >> 1);
        const int srcB = srcA + 2;
        #pragma unroll
        for (int ks = 0; ks < 8; ks++) {
            uint32_t af[4];
            {
                float t0 = __shfl_sync(0xffffffffu, sa[ks][0], srcA);
                float t1 = __shfl_sync(0xffffffffu, sa[ks][1], srcA);
                float t2 = __shfl_sync(0xffffffffu, sa[ks][2], srcA);
                float t3 = __shfl_sync(0xffffffffu, sa[ks][3], srcA);
                af[0] = __float_as_uint((qc & 1) ? t1 : t0);
                af[1] = __float_as_uint((qc & 1) ? t3 : t2);
                t0 = __shfl_sync(0xffffffffu, sa[ks][0], srcB);
                t1 = __shfl_sync(0xffffffffu, sa[ks][1], srcB);
                t2 = __shfl_sync(0xffffffffu, sa[ks][2], srcB);
                t3 = __shfl_sync(0xffffffffu, sa[ks][3], srcB);
                af[2] = __float_as_uint((qc & 1) ? t1 : t0);
                af[3] = __float_as_uint((qc & 1) ? t3 : t2);
            }
            #pragma unroll
            for (int na = 0; na < 8; na++) {
                uint32_t bf[2];
                bf[0] = __float_as_uint(Vst[(ks * 8 + qc) * VST + na * 8 + qr]);
                bf[1] = __float_as_uint(Vst[(ks * 8 + qc + 4) * VST + na * 8 + qr]);
                MMA_TF32(o[na], af, bf);
            }
        }
        __syncthreads();
        st ^= 1;
    }

    // ---- epilogue: O /= l, write ----
    const float il_lo = 1.f / l_lo;
    const float il_hi = 1.f / l_hi;
    #pragma unroll
    for (int na = 0; na < 8; na++) {
        const int col = na * 8 + qc * 2;
        *reinterpret_cast<float2*>(Og + (long long)rw * CC + col) =
            make_float2(o[na][0] * il_lo, o[na][1] * il_lo);
        *reinterpret_cast<float2*>(Og + (long long)(rw + 8) * CC + col) =
            make_float2(o[na][2] * il_hi, o[na][3] * il_hi);
    }
}

// ---------------- LayerNorm (+optional modulation) ----------------
__global__ __launch_bounds__(256)
void ln_kernel(const float* __restrict__ x, float* __restrict__ out,
               const float* __restrict__ gamma, const float* __restrict__ beta,
               int gstride, float add_one)
{
    const int row = blockIdx.x;
    const int b   = row / LL;
    const float* px = x + (long long)row * CC;
    float*       po = out + (long long)row * CC;
    const int t = threadIdx.x;

    float v[4];
    float s = 0.f, s2 = 0.f;
    #pragma unroll
    for (int i = 0; i < 4; i++) {
        v[i] = px[t + i * 256];
        s  += v[i];
        s2 += v[i] * v[i];
    }
    __shared__ float sred[2][8];
    #pragma unroll
    for (int o = 16; o; o >>= 1) {
        s  += __shfl_xor_sync(0xffffffffu, s,  o);
        s2 += __shfl_xor_sync(0xffffffffu, s2, o);
    }
    if ((t & 31) == 0) { sred[0][t >> 5] = s; sred[1][t >> 5] = s2; }
    __syncthreads();
    s = 0.f; s2 = 0.f;
    #pragma unroll
    for (int w = 0; w < 8; w++) { s += sred[0][w]; s2 += sred[1][w]; }

    const float mu  = s * (1.f / CC);
    const float var = s2 * (1.f / CC) - mu * mu;
    const float r   = rsqrtf(var + EPS);

    const float* g  = gamma + (long long)b * gstride;
    const float* be = beta  + (long long)b * gstride;
    #pragma unroll
    for (int i = 0; i < 4; i++) {
        int c = t + i * 256;
        po[c] = (v[i] - mu) * r * (add_one + g[c]) + be[c];
    }
}

// ---------------- residual (+ optional per-(b,c) gate) ----------------
__global__ __launch_bounds__(256)
void residual_kernel(const float* __restrict__ base, const float* __restrict__ tt,
                     const float* __restrict__ gate, int gstride,
                     float* __restrict__ out)
{
    long long i = (long long)blockIdx.x * 256 + threadIdx.x;
    float g = 1.f;
    if (gate) {
        int b = (int)(i >> 21);
        int c = (int)(i & 1023);
        g = gate[b * gstride + c];
    }
    out[i] = base[i] + tt[i] * g;
}

// ---------------- adaLN: ada = silu(mod) @ w_ada + b_ada ----------------
__global__ __launch_bounds__(256)
void ada_kernel(const float* __restrict__ mod, const float* __restrict__ w,
                const float* __restrict__ bias, float* __restrict__ ada)
{
    __shared__ float sm[CC];
    const int b = blockIdx.y;
    const int j = blockIdx.x * 256 + threadIdx.x;
    #pragma unroll
    for (int i = 0; i < 4; i++) {
        int c = threadIdx.x + i * 256;
        float m = mod[b * CC + c];
        sm[c] = m / (1.f + expf(-m));
    }
    __syncthreads();
    float acc = 0.f;
    for (int c = 0; c < CC; c++)
        acc = fmaf(sm[c], w[(long long)c * SIXC + j], acc);
    ada[(long long)b * SIXC + j] = acc + bias[j];
}

// ---------------- launch ----------------
extern "C" void kernel_launch(void* const* d_in, const int* in_sizes, int n_in,
                              void* d_out, int out_size)
{
    const float* x      = (const float*)d_in[0];
    const float* mod    = (const float*)d_in[1];
    const float* ctx    = (const float*)d_in[2];
    const float* w_ada  = (const float*)d_in[3];
    const float* b_ada  = (const float*)d_in[4];
    const float* w_qkv  = (const float*)d_in[5];
    const float* b_qkv  = (const float*)d_in[6];
    const float* w_so   = (const float*)d_in[7];
    const float* b_so   = (const float*)d_in[8];
    const float* gn2    = (const float*)d_in[9];
    const float* bn2    = (const float*)d_in[10];
    const float* w_cq   = (const float*)d_in[11];
    const float* b_cq   = (const float*)d_in[12];
    const float* w_ckv  = (const float*)d_in[13];
    const float* b_ckv  = (const float*)d_in[14];
    const float* w_co   = (const float*)d_in[15];
    const float* b_co   = (const float*)d_in[16];
    const float* w_m1   = (const float*)d_in[17];
    const float* b_m1   = (const float*)d_in[18];
    const float* w_m2   = (const float*)d_in[19];
    const float* b_m2   = (const float*)d_in[20];
    float* out = (float*)d_out;

    float *ph, *pqkv, *pS, *pO, *pt, *pkv, *pada;
    cudaGetSymbolAddress((void**)&ph,   g_h);
    cudaGetSymbolAddress((void**)&pqkv, g_qkv);
    cudaGetSymbolAddress((void**)&pS,   g_S);
    cudaGetSymbolAddress((void**)&pO,   g_O);
    cudaGetSymbolAddress((void**)&pt,   g_t);
    cudaGetSymbolAddress((void**)&pkv,  g_kv);
    cudaGetSymbolAddress((void**)&pada, g_ada);

    cudaFuncSetAttribute(flash_kernel,
                         cudaFuncAttributeMaxDynamicSharedMemorySize, FLASH_SMEM);

    const long long totalBLC = (long long)MT * CC;
    const int resGrid = (int)(totalBLC / 256);

    // 1. adaLN modulation
    ada_kernel<<<dim3(SIXC / 256, BB), 256>>>(mod, w_ada, b_ada, pada);

    // ===== MSA branch =====
    ln_kernel<<<MT, 256>>>(x, ph, pada + CC, pada, SIXC, 1.f);
    tgemm_kernel<0, 128, 0><<<dim3(3 * CC / 128, MT / TBM, 1), 256>>>(
        ph, w_qkv, b_qkv, pqkv, MT, 3 * CC, CC, CC, 3 * CC, 3 * CC, 0, 0, 0, 1.f);

    // flash self-attention: Q/K/V interleaved in g_qkv (ld 3C)
    flash_kernel<<<dim3(LL / 128, HH, BB), 256, FLASH_SMEM>>>(
        pqkv, pqkv + CC, pqkv + 2 * CC, pO, 3 * CC, 3 * CC, LL, LL / 64);

    tgemm_kernel<0, 128, 0><<<dim3(CC / 128, MT / TBM, 1), 256>>>(
        pO, w_so, b_so, pt, MT, CC, CC, CC, CC, CC, 0, 0, 0, 1.f);
    residual_kernel<<<resGrid, 256>>>(x, pt, pada + 2 * CC, SIXC, out);

    // ===== MCA branch =====
    ln_kernel<<<MT, 256>>>(out, ph, gn2, bn2, 0, 0.f);
    tgemm_kernel<0, 128, 0><<<dim3(CC / 128, MT / TBM, 1), 256>>>(
        ph, w_cq, b_cq, pqkv, MT, CC, CC, CC, CC, CC, 0, 0, 0, 1.f);
    tgemm_kernel<0, 128, 0><<<dim3(2 * CC / 128, (BB * LCC) / TBM, 1), 256>>>(
        ctx, w_ckv, b_ckv, pkv, BB * LCC, 2 * CC, CTXC, CTXC, 2 * CC, 2 * CC, 0, 0, 0, 1.f);

    // flash cross-attention: Q in g_qkv (ld C), K/V in g_kv (ld 2C)
    flash_kernel<<<dim3(LL / 128, HH, BB), 256, FLASH_SMEM>>>(
        pqkv, pkv, pkv + CC, pO, CC, 2 * CC, LCC, LCC / 64);

    tgemm_kernel<0, 128, 0><<<dim3(CC / 128, MT / TBM, 1), 256>>>(
        pO, w_co, b_co, pt, MT, CC, CC, CC, CC, CC, 0, 0, 0, 1.f);
    residual_kernel<<<resGrid, 256>>>(out, pt, nullptr, 0, out);

    // ===== FFN branch =====
    ln_kernel<<<MT, 256>>>(out, ph, pada + 4 * CC, pada + 3 * CC, SIXC, 1.f);
    tgemm_kernel<0, 128, 1><<<dim3(4 * CC / 128, MT / TBM, 1), 256>>>(
        ph, w_m1, b_m1, pS, MT, 4 * CC, CC, CC, 4 * CC, 4 * CC, 0, 0, 0, 1.f);
    tgemm_kernel<0, 128, 0><<<dim3(CC / 128, MT / TBM, 1), 256>>>(
        pS, w_m2, b_m2, pt, MT, CC, 4 * CC, 4 * CC, CC, CC, 0, 0, 0, 1.f);
    residual_kernel<<<resGrid, 256>>>(out, pt, pada + 5 * CC, SIXC, out);
}

// round 6
// speedup vs baseline: 8.1722x; 1.7470x over previous
#include <cuda_runtime.h>
#include <cuda_fp16.h>
#include <math.h>
#include <stdint.h>

// ---------------- problem constants ----------------
#define BB   4
#define LL   2048
#define LCC  512
#define CC   1024
#define CTXC 1024
#define HH   16
#define DD   64
#define SIXC (6*CC)
#define MT   (BB*LL)          // 8192 token rows
#define EPS  1e-6f
#define ATT_SCALE 0.125f      // 1/sqrt(64)

// ---------------- device scratch (no allocations allowed) ----------------
__device__ __half g_hh  [(long long)MT * CC];          // LN outputs (half)
__device__ __half g_hqkv[(long long)MT * 3 * CC];      // qkv / q2 (half)
__device__ __half g_hS  [(long long)MT * 4 * CC];      // FFN mid (half)
__device__ __half g_hO  [(long long)MT * CC];          // attention out (half)
__device__ __half g_hkv [(long long)BB * LCC * 2 * CC];// cross kv (half)
__device__ __half g_hctx[(long long)BB * LCC * CTXC];  // context (half)
__device__ __half g_hwt [16 * 1024 * 1024];            // transposed half weights [N,K]
__device__ float  g_t  [(long long)MT * CC];           // projection temp (fp32)
__device__ float  g_ada[(long long)BB * SIXC];         // modulation

// ---------------- PTX helpers ----------------
__device__ __forceinline__ void cp_async16(void* smem, const void* gmem) {
    uint32_t s = (uint32_t)__cvta_generic_to_shared(smem);
    asm volatile("cp.async.cg.shared.global [%0], [%1], 16;\n" :: "r"(s), "l"(gmem));
}
#define CP_COMMIT() asm volatile("cp.async.commit_group;\n" ::: "memory")
#define CP_WAIT1()  asm volatile("cp.async.wait_group 1;\n" ::: "memory")

#define MMA_F16(d, a, b)                                                      \
    asm volatile("mma.sync.aligned.m16n8k16.row.col.f32.f16.f16.f32 "         \
                 "{%0,%1,%2,%3}, {%4,%5,%6,%7}, {%8,%9}, {%0,%1,%2,%3};\n"    \
                 : "+f"((d)[0]), "+f"((d)[1]), "+f"((d)[2]), "+f"((d)[3])     \
                 : "r"((a)[0]), "r"((a)[1]), "r"((a)[2]), "r"((a)[3]),        \
                   "r"((b)[0]), "r"((b)[1]))

#define LDMATRIX_X4_TRANS(r0, r1, r2, r3, addr)                               \
    asm volatile("ldmatrix.sync.aligned.m8n8.x4.trans.shared.b16 "            \
                 "{%0,%1,%2,%3}, [%4];"                                       \
                 : "=r"(r0), "=r"(r1), "=r"(r2), "=r"(r3) : "r"(addr))

__device__ __forceinline__ uint32_t pack_h2(float lo, float hi) {
    __half2 h = __floats2half2_rn(lo, hi);
    return *reinterpret_cast<uint32_t*>(&h);
}
__device__ __forceinline__ uint32_t lds_u32(const __half* p) {
    return *reinterpret_cast<const uint32_t*>(p);
}
__device__ __forceinline__ float gelu_exact(float x) {
    return 0.5f * x * (1.f + erff(x * 0.70710678118654752f));
}

// ---------------- fp16 tensor-core GEMM (TRANSB only) ----------------
// C[M,N] = act(A[M,K] @ Bt[N,K]^T + bias).  A,Bt half row-major.
// M%128==0, N%128==0, K%32==0.
#define HBM_T 128
#define HBK   32
#define HST   40   // smem row stride in halves (80B: conflict-free frags)

template<int OUT_HALF, int ACT>
__global__ __launch_bounds__(256, 2)
void hgemm_kernel(const __half* __restrict__ A, const __half* __restrict__ Bt,
                  const float* __restrict__ bias, void* __restrict__ Cp,
                  int K, int ldc)
{
    __shared__ __half As[2][HBM_T * HST];
    __shared__ __half Bs[2][HBM_T * HST];

    const int t    = threadIdx.x;
    const int m0   = blockIdx.y * HBM_T;
    const int n0   = blockIdx.x * HBM_T;
    const int lane = t & 31;
    const int warp = t >> 5;
    const int qr   = lane >> 2;
    const int qc   = lane & 3;
    const int wm   = warp >> 2;          // 0..1
    const int wn   = warp & 3;           // 0..3
    const int rb   = wm * 64;
    const int nb   = wn * 32;

    float acc[4][4][4];
    #pragma unroll
    for (int i = 0; i < 4; i++)
        #pragma unroll
        for (int j = 0; j < 4; j++)
            #pragma unroll
            for (int r = 0; r < 4; r++) acc[i][j][r] = 0.f;

    const int lr = t >> 1;               // 0..127
    const int lk = (t & 1) * 16;         // 0 or 16 halves

    auto load_tiles = [&](int kt, int st) {
        const __half* ga = A  + (long long)(m0 + lr) * K + kt + lk;
        const __half* gb = Bt + (long long)(n0 + lr) * K + kt + lk;
        __half* sa = &As[st][lr * HST + lk];
        __half* sb = &Bs[st][lr * HST + lk];
        cp_async16(sa,     ga);
        cp_async16(sa + 8, ga + 8);
        cp_async16(sb,     gb);
        cp_async16(sb + 8, gb + 8);
    };

    load_tiles(0, 0);
    CP_COMMIT();

    int st = 0;
    for (int kt = 0; kt < K; kt += HBK) {
        if (kt + HBK < K) load_tiles(kt + HBK, st ^ 1);
        CP_COMMIT();
        CP_WAIT1();
        __syncthreads();

        #pragma unroll
        for (int ks = 0; ks < 2; ks++) {
            const int kb = ks * 16 + 2 * qc;
            uint32_t af[4][4], bf[4][2];
            #pragma unroll
            for (int ma = 0; ma < 4; ma++) {
                const int r = rb + ma * 16 + qr;
                af[ma][0] = lds_u32(&As[st][r * HST + kb]);
                af[ma][1] = lds_u32(&As[st][(r + 8) * HST + kb]);
                af[ma][2] = lds_u32(&As[st][r * HST + kb + 8]);
                af[ma][3] = lds_u32(&As[st][(r + 8) * HST + kb + 8]);
            }
            #pragma unroll
            for (int na = 0; na < 4; na++) {
                const int n = nb + na * 8 + qr;
                bf[na][0] = lds_u32(&Bs[st][n * HST + kb]);
                bf[na][1] = lds_u32(&Bs[st][n * HST + kb + 8]);
            }
            #pragma unroll
            for (int ma = 0; ma < 4; ma++)
                #pragma unroll
                for (int na = 0; na < 4; na++)
                    MMA_F16(acc[ma][na], af[ma], bf[na]);
        }
        __syncthreads();
        st ^= 1;
    }

    // ---- epilogue ----
    #pragma unroll
    for (int ma = 0; ma < 4; ma++) {
        const int row0 = m0 + rb + ma * 16 + qr;
        #pragma unroll
        for (int na = 0; na < 4; na++) {
            const int col0 = n0 + nb + na * 8 + qc * 2;
            const float b0 = bias[col0], b1 = bias[col0 + 1];
            float v00 = acc[ma][na][0] + b0;
            float v01 = acc[ma][na][1] + b1;
            float v10 = acc[ma][na][2] + b0;
            float v11 = acc[ma][na][3] + b1;
            if (ACT) {
                v00 = gelu_exact(v00); v01 = gelu_exact(v01);
                v10 = gelu_exact(v10); v11 = gelu_exact(v11);
            }
            if (OUT_HALF) {
                __half* C = (__half*)Cp;
                *reinterpret_cast<__half2*>(C + (long long)row0 * ldc + col0) =
                    __floats2half2_rn(v00, v01);
                *reinterpret_cast<__half2*>(C + (long long)(row0 + 8) * ldc + col0) =
                    __floats2half2_rn(v10, v11);
            } else {
                float* C = (float*)Cp;
                *reinterpret_cast<float2*>(C + (long long)row0 * ldc + col0) =
                    make_float2(v00, v01);
                *reinterpret_cast<float2*>(C + (long long)(row0 + 8) * ldc + col0) =
                    make_float2(v10, v11);
            }
        }
    }
}

// ---------------- fp16 flash attention ----------------
// Per CTA: one (batch=z, head=y, 128-row Q tile=x). 8 warps x 16 rows. BC=64.
#define FST 72   // smem row stride (halves) for Q/K/V
#define FLASH_SMEM ((128 * FST + 2 * 64 * FST + 2 * 64 * FST) * 2)

__global__ __launch_bounds__(256, 2)
void flash_kernel(const __half* __restrict__ Qp, const __half* __restrict__ Kp,
                  const __half* __restrict__ Vp, __half* __restrict__ Op,
                  int qld, int kld, int kvRows, int nkv)
{
    extern __shared__ __half fsm[];
    __half* Qs = fsm;                    // 128*FST
    __half* Ks = Qs + 128 * FST;         // 2 stages 64*FST  ([kv][d])
    __half* Vs = Ks + 2 * 64 * FST;      // 2 stages 64*FST  ([kv][d])

    const int t    = threadIdx.x;
    const int lane = t & 31;
    const int warp = t >> 5;
    const int qr   = lane >> 2;
    const int qc   = lane & 3;

    const int b = blockIdx.z, h = blockIdx.y;
    const __half* Qg = Qp + (long long)(b * LL + blockIdx.x * 128) * qld + h * DD;
    const __half* Kg = Kp + (long long)b * kvRows * kld + h * DD;
    const __half* Vg = Vp + (long long)b * kvRows * kld + h * DD;
    __half*       Og = Op + (long long)(b * LL + blockIdx.x * 128) * CC + h * DD;

    // ---- load Q tile ----
    {
        const int r = t >> 1, kc = (t & 1) * 32;
        const __half* g = Qg + (long long)r * qld + kc;
        __half* s = Qs + r * FST + kc;
        #pragma unroll
        for (int i = 0; i < 4; i++) cp_async16(s + i * 8, g + i * 8);
    }
    CP_COMMIT();

    auto load_kv = [&](int it, int stg) {
        const int kv0 = it * 64;
        const int r = t >> 2, c = (t & 3) * 16;
        {
            const __half* g = Kg + (long long)(kv0 + r) * kld + c;
            __half* s = Ks + stg * (64 * FST) + r * FST + c;
            cp_async16(s,     g);
            cp_async16(s + 8, g + 8);
        }
        {
            const __half* g = Vg + (long long)(kv0 + r) * kld + c;
            __half* s = Vs + stg * (64 * FST) + r * FST + c;
            cp_async16(s,     g);
            cp_async16(s + 8, g + 8);
        }
    };

    load_kv(0, 0);
    CP_COMMIT();

    const int rw = warp * 16 + qr;

    // V ldmatrix per-lane base offset (halves): group g = lane>>3
    const int vg = lane >> 3;
    const int v_off = ((vg & 1) * 8 + (lane & 7)) * FST + (vg >> 1) * 8;

    float o[8][4];
    #pragma unroll
    for (int na = 0; na < 8; na++)
        #pragma unroll
        for (int j = 0; j < 4; j++) o[na][j] = 0.f;
    float m_lo = -INFINITY, m_hi = -INFINITY;
    float l_lo = 0.f, l_hi = 0.f;

    int stg = 0;
    for (int it = 0; it < nkv; it++) {
        if (it + 1 < nkv) load_kv(it + 1, stg ^ 1);
        CP_COMMIT();
        CP_WAIT1();
        __syncthreads();

        const __half* Kst = Ks + stg * (64 * FST);
        const __half* Vst = Vs + stg * (64 * FST);

        // ---- S = Q K^T  (4 k16 steps over D=64) ----
        float sa[8][4];
        #pragma unroll
        for (int na = 0; na < 8; na++)
            #pragma unroll
            for (int j = 0; j < 4; j++) sa[na][j] = 0.f;

        #pragma unroll
        for (int ks = 0; ks < 4; ks++) {
            const int kb = ks * 16 + 2 * qc;
            uint32_t af[4];
            af[0] = lds_u32(&Qs[rw * FST + kb]);
            af[1] = lds_u32(&Qs[(rw + 8) * FST + kb]);
            af[2] = lds_u32(&Qs[rw * FST + kb + 8]);
            af[3] = lds_u32(&Qs[(rw + 8) * FST + kb + 8]);
            #pragma unroll
            for (int na = 0; na < 8; na++) {
                uint32_t bf[2];
                bf[0] = lds_u32(&Kst[(na * 8 + qr) * FST + kb]);
                bf[1] = lds_u32(&Kst[(na * 8 + qr) * FST + kb + 8]);
                MMA_F16(sa[na], af, bf);
            }
        }

        // ---- online softmax ----
        float tm_lo = -INFINITY, tm_hi = -INFINITY;
        #pragma unroll
        for (int na = 0; na < 8; na++) {
            sa[na][0] *= ATT_SCALE; sa[na][1] *= ATT_SCALE;
            sa[na][2] *= ATT_SCALE; sa[na][3] *= ATT_SCALE;
            tm_lo = fmaxf(tm_lo, fmaxf(sa[na][0], sa[na][1]));
            tm_hi = fmaxf(tm_hi, fmaxf(sa[na][2], sa[na][3]));
        }
        tm_lo = fmaxf(tm_lo, __shfl_xor_sync(0xffffffffu, tm_lo, 1));
        tm_lo = fmaxf(tm_lo, __shfl_xor_sync(0xffffffffu, tm_lo, 2));
        tm_hi = fmaxf(tm_hi, __shfl_xor_sync(0xffffffffu, tm_hi, 1));
        tm_hi = fmaxf(tm_hi, __shfl_xor_sync(0xffffffffu, tm_hi, 2));

        const float mn_lo = fmaxf(m_lo, tm_lo);
        const float mn_hi = fmaxf(m_hi, tm_hi);
        const float sc_lo = __expf(m_lo - mn_lo);
        const float sc_hi = __expf(m_hi - mn_hi);
        m_lo = mn_lo; m_hi = mn_hi;

        float rl = 0.f, rh = 0.f;
        #pragma unroll
        for (int na = 0; na < 8; na++) {
            sa[na][0] = __expf(sa[na][0] - mn_lo);
            sa[na][1] = __expf(sa[na][1] - mn_lo);
            sa[na][2] = __expf(sa[na][2] - mn_hi);
            sa[na][3] = __expf(sa[na][3] - mn_hi);
            rl += sa[na][0] + sa[na][1];
            rh += sa[na][2] + sa[na][3];
        }
        rl += __shfl_xor_sync(0xffffffffu, rl, 1);
        rl += __shfl_xor_sync(0xffffffffu, rl, 2);
        rh += __shfl_xor_sync(0xffffffffu, rh, 1);
        rh += __shfl_xor_sync(0xffffffffu, rh, 2);
        l_lo = l_lo * sc_lo + rl;
        l_hi = l_hi * sc_hi + rh;

        #pragma unroll
        for (int na = 0; na < 8; na++) {
            o[na][0] *= sc_lo; o[na][1] *= sc_lo;
            o[na][2] *= sc_hi; o[na][3] *= sc_hi;
        }

        // ---- O += P V : P packed to fp16 A-frags directly (no shuffles) ----
        const uint32_t vst_base = (uint32_t)__cvta_generic_to_shared(Vst) + v_off * 2;
        #pragma unroll
        for (int kblk = 0; kblk < 4; kblk++) {
            uint32_t pa[4];
            pa[0] = pack_h2(sa[2 * kblk][0],     sa[2 * kblk][1]);
            pa[1] = pack_h2(sa[2 * kblk][2],     sa[2 * kblk][3]);
            pa[2] = pack_h2(sa[2 * kblk + 1][0], sa[2 * kblk + 1][1]);
            pa[3] = pack_h2(sa[2 * kblk + 1][2], sa[2 * kblk + 1][3]);
            #pragma unroll
            for (int nb2 = 0; nb2 < 4; nb2++) {
                uint32_t r0, r1, r2, r3;
                const uint32_t addr = vst_base + (kblk * 16 * FST + nb2 * 16) * 2;
                LDMATRIX_X4_TRANS(r0, r1, r2, r3, addr);
                uint32_t bf0[2] = {r0, r1};
                uint32_t bf1[2] = {r2, r3};
                MMA_F16(o[2 * nb2],     pa, bf0);
                MMA_F16(o[2 * nb2 + 1], pa, bf1);
            }
        }
        __syncthreads();
        stg ^= 1;
    }

    // ---- epilogue: O /= l, write half ----
    const float il_lo = 1.f / l_lo;
    const float il_hi = 1.f / l_hi;
    #pragma unroll
    for (int na = 0; na < 8; na++) {
        const int col = na * 8 + qc * 2;
        *reinterpret_cast<__half2*>(Og + (long long)rw * CC + col) =
            __floats2half2_rn(o[na][0] * il_lo, o[na][1] * il_lo);
        *reinterpret_cast<__half2*>(Og + (long long)(rw + 8) * CC + col) =
            __floats2half2_rn(o[na][2] * il_hi, o[na][3] * il_hi);
    }
}

// ---------------- LayerNorm (+optional modulation), half output ----------------
__global__ __launch_bounds__(256)
void ln_kernel(const float* __restrict__ x, __half* __restrict__ out,
               const float* __restrict__ gamma, const float* __restrict__ beta,
               int gstride, float add_one)
{
    const int row = blockIdx.x;
    const int b   = row / LL;
    const float* px = x + (long long)row * CC;
    __half*      po = out + (long long)row * CC;
    const int t = threadIdx.x;

    float v[4];
    float s = 0.f, s2 = 0.f;
    #pragma unroll
    for (int i = 0; i < 4; i++) {
        v[i] = px[t + i * 256];
        s  += v[i];
        s2 += v[i] * v[i];
    }
    __shared__ float sred[2][8];
    #pragma unroll
    for (int o = 16; o; o >>= 1) {
        s  += __shfl_xor_sync(0xffffffffu, s,  o);
        s2 += __shfl_xor_sync(0xffffffffu, s2, o);
    }
    if ((t & 31) == 0) { sred[0][t >> 5] = s; sred[1][t >> 5] = s2; }
    __syncthreads();
    s = 0.f; s2 = 0.f;
    #pragma unroll
    for (int w = 0; w < 8; w++) { s += sred[0][w]; s2 += sred[1][w]; }

    const float mu  = s * (1.f / CC);
    const float var = s2 * (1.f / CC) - mu * mu;
    const float r   = rsqrtf(var + EPS);

    const float* g  = gamma + (long long)b * gstride;
    const float* be = beta  + (long long)b * gstride;
    #pragma unroll
    for (int i = 0; i < 4; i++) {
        int c = t + i * 256;
        po[c] = __float2half((v[i] - mu) * r * (add_one + g[c]) + be[c]);
    }
}

// ---------------- residual (+ optional per-(b,c) gate) ----------------
__global__ __launch_bounds__(256)
void residual_kernel(const float* __restrict__ base, const float* __restrict__ tt,
                     const float* __restrict__ gate, int gstride,
                     float* __restrict__ out)
{
    long long i = (long long)blockIdx.x * 256 + threadIdx.x;
    float g = 1.f;
    if (gate) {
        int b = (int)(i >> 21);
        int c = (int)(i & 1023);
        g = gate[b * gstride + c];
    }
    out[i] = base[i] + tt[i] * g;
}

// ---------------- adaLN: ada = silu(mod) @ w_ada + b_ada ----------------
__global__ __launch_bounds__(256)
void ada_kernel(const float* __restrict__ mod, const float* __restrict__ w,
                const float* __restrict__ bias, float* __restrict__ ada)
{
    __shared__ float sm[CC];
    const int b = blockIdx.y;
    const int j = blockIdx.x * 256 + threadIdx.x;
    #pragma unroll
    for (int i = 0; i < 4; i++) {
        int c = threadIdx.x + i * 256;
        float m = mod[b * CC + c];
        sm[c] = m / (1.f + expf(-m));
    }
    __syncthreads();
    float acc = 0.f;
    for (int c = 0; c < CC; c++)
        acc = fmaf(sm[c], w[(long long)c * SIXC + j], acc);
    ada[(long long)b * SIXC + j] = acc + bias[j];
}

// ---------------- weight convert+transpose: fp32 [K][N] -> half [N][K] ----------------
__global__ __launch_bounds__(256)
void wconv_kernel(const float* __restrict__ in, __half* __restrict__ outp,
                  int K, int N)
{
    __shared__ float tile[32][33];
    const int kb = blockIdx.y * 32, nb = blockIdx.x * 32;
    const int tx = threadIdx.x, ty = threadIdx.y;   // 32 x 8
    #pragma unroll
    for (int i = 0; i < 32; i += 8)
        tile[ty + i][tx] = in[(long long)(kb + ty + i) * N + nb + tx];
    __syncthreads();
    #pragma unroll
    for (int i = 0; i < 32; i += 8)
        outp[(long long)(nb + ty + i) * K + kb + tx] = __float2half(tile[tx][ty + i]);
}

// ---------------- fp32 -> half elementwise ----------------
__global__ __launch_bounds__(256)
void f2h_kernel(const float* __restrict__ in, __half* __restrict__ outp)
{
    long long i = (long long)blockIdx.x * 1024 + threadIdx.x * 4;
    float4 v = *reinterpret_cast<const float4*>(in + i);
    __half2* o = reinterpret_cast<__half2*>(outp + i);
    o[0] = __floats2half2_rn(v.x, v.y);
    o[1] = __floats2half2_rn(v.z, v.w);
}

// ---------------- launch ----------------
extern "C" void kernel_launch(void* const* d_in, const int* in_sizes, int n_in,
                              void* d_out, int out_size)
{
    const float* x      = (const float*)d_in[0];
    const float* mod    = (const float*)d_in[1];
    const float* ctx    = (const float*)d_in[2];
    const float* w_ada  = (const float*)d_in[3];
    const float* b_ada  = (const float*)d_in[4];
    const float* w_qkv  = (const float*)d_in[5];
    const float* b_qkv  = (const float*)d_in[6];
    const float* w_so   = (const float*)d_in[7];
    const float* b_so   = (const float*)d_in[8];
    const float* gn2    = (const float*)d_in[9];
    const float* bn2    = (const float*)d_in[10];
    const float* w_cq   = (const float*)d_in[11];
    const float* b_cq   = (const float*)d_in[12];
    const float* w_ckv  = (const float*)d_in[13];
    const float* b_ckv  = (const float*)d_in[14];
    const float* w_co   = (const float*)d_in[15];
    const float* b_co   = (const float*)d_in[16];
    const float* w_m1   = (const float*)d_in[17];
    const float* b_m1   = (const float*)d_in[18];
    const float* w_m2   = (const float*)d_in[19];
    const float* b_m2   = (const float*)d_in[20];
    float* out = (float*)d_out;

    __half *hh, *hqkv, *hS, *hO, *hkv, *hctx, *hwt;
    float *pt, *pada;
    cudaGetSymbolAddress((void**)&hh,   g_hh);
    cudaGetSymbolAddress((void**)&hqkv, g_hqkv);
    cudaGetSymbolAddress((void**)&hS,   g_hS);
    cudaGetSymbolAddress((void**)&hO,   g_hO);
    cudaGetSymbolAddress((void**)&hkv,  g_hkv);
    cudaGetSymbolAddress((void**)&hctx, g_hctx);
    cudaGetSymbolAddress((void**)&hwt,  g_hwt);
    cudaGetSymbolAddress((void**)&pt,   g_t);
    cudaGetSymbolAddress((void**)&pada, g_ada);

    __half* wt_qkv = hwt;                     // 3072x1024
    __half* wt_so  = wt_qkv + 3072 * 1024;    // 1024x1024
    __half* wt_cq  = wt_so  + 1024 * 1024;    // 1024x1024
    __half* wt_ckv = wt_cq  + 1024 * 1024;    // 2048x1024
    __half* wt_co  = wt_ckv + 2048 * 1024;    // 1024x1024
    __half* wt_m1  = wt_co  + 1024 * 1024;    // 4096x1024
    __half* wt_m2  = wt_m1  + 4096 * 1024;    // 1024x4096

    cudaFuncSetAttribute(flash_kernel,
                         cudaFuncAttributeMaxDynamicSharedMemorySize, FLASH_SMEM);

    const long long totalBLC = (long long)MT * CC;
    const int resGrid = (int)(totalBLC / 256);
    const dim3 tb(32, 8);

    // ---- weight converts ([K,N] fp32 -> [N,K] half) + ctx convert ----
    wconv_kernel<<<dim3(3072 / 32, 1024 / 32), tb>>>(w_qkv, wt_qkv, 1024, 3072);
    wconv_kernel<<<dim3(1024 / 32, 1024 / 32), tb>>>(w_so,  wt_so,  1024, 1024);
    wconv_kernel<<<dim3(1024 / 32, 1024 / 32), tb>>>(w_cq,  wt_cq,  1024, 1024);
    wconv_kernel<<<dim3(2048 / 32, 1024 / 32), tb>>>(w_ckv, wt_ckv, 1024, 2048);
    wconv_kernel<<<dim3(1024 / 32, 1024 / 32), tb>>>(w_co,  wt_co,  1024, 1024);
    wconv_kernel<<<dim3(4096 / 32, 1024 / 32), tb>>>(w_m1,  wt_m1,  1024, 4096);
    wconv_kernel<<<dim3(1024 / 32, 4096 / 32), tb>>>(w_m2,  wt_m2,  4096, 1024);
    f2h_kernel<<<(int)((long long)BB * LCC * CTXC / 1024), 256>>>(ctx, hctx);

    // 1. adaLN modulation
    ada_kernel<<<dim3(SIXC / 256, BB), 256>>>(mod, w_ada, b_ada, pada);

    // ===== MSA branch =====
    ln_kernel<<<MT, 256>>>(x, hh, pada + CC, pada, SIXC, 1.f);
    hgemm_kernel<1, 0><<<dim3(3 * CC / 128, MT / 128), 256>>>(
        hh, wt_qkv, b_qkv, hqkv, CC, 3 * CC);

    flash_kernel<<<dim3(LL / 128, HH, BB), 256, FLASH_SMEM>>>(
        hqkv, hqkv + CC, hqkv + 2 * CC, hO, 3 * CC, 3 * CC, LL, LL / 64);

    hgemm_kernel<0, 0><<<dim3(CC / 128, MT / 128), 256>>>(
        hO, wt_so, b_so, pt, CC, CC);
    residual_kernel<<<resGrid, 256>>>(x, pt, pada + 2 * CC, SIXC, out);

    // ===== MCA branch =====
    ln_kernel<<<MT, 256>>>(out, hh, gn2, bn2, 0, 0.f);
    hgemm_kernel<1, 0><<<dim3(CC / 128, MT / 128), 256>>>(
        hh, wt_cq, b_cq, hqkv, CC, CC);
    hgemm_kernel<1, 0><<<dim3(2 * CC / 128, (BB * LCC) / 128), 256>>>(
        hctx, wt_ckv, b_ckv, hkv, CTXC, 2 * CC);

    flash_kernel<<<dim3(LL / 128, HH, BB), 256, FLASH_SMEM>>>(
        hqkv, hkv, hkv + CC, hO, CC, 2 * CC, LCC, LCC / 64);

    hgemm_kernel<0, 0><<<dim3(CC / 128, MT / 128), 256>>>(
        hO, wt_co, b_co, pt, CC, CC);
    residual_kernel<<<resGrid, 256>>>(out, pt, nullptr, 0, out);

    // ===== FFN branch =====
    ln_kernel<<<MT, 256>>>(out, hh, pada + 4 * CC, pada + 3 * CC, SIXC, 1.f);
    hgemm_kernel<1, 1><<<dim3(4 * CC / 128, MT / 128), 256>>>(
        hh, wt_m1, b_m1, hS, CC, 4 * CC);
    hgemm_kernel<0, 0><<<dim3(CC / 128, MT / 128), 256>>>(
        hS, wt_m2, b_m2, pt, 4 * CC, CC);
    residual_kernel<<<resGrid, 256>>>(out, pt, pada + 5 * CC, SIXC, out);
}